// round 5
// baseline (speedup 1.0000x reference)
#include <cuda_runtime.h>
#include <cuda_bf16.h>
#include <math.h>

// ---------------- problem constants ----------------
#define BATCH 2
#define SEQ   2048
#define HID   2048
#define NH    16
#define DQK   192      // 128 nope + 64 rope
#define DV    128
#define QLORA 1536
#define KVLORA 512
#define ROPE_D 64
#define TOK   (BATCH*SEQ)          // 4096
#define BHN   (BATCH*NH)           // 32

// ---------------- scratch (device globals; no runtime alloc) -------------
__device__ float g_q1  [(size_t)TOK * QLORA];
__device__ float g_q   [(size_t)TOK * (NH*DQK)];
__device__ float g_c   [(size_t)TOK * (KVLORA+ROPE_D)];
__device__ float g_ckvn[(size_t)TOK * KVLORA];
__device__ float g_kv  [(size_t)TOK * (NH*256)];
__device__ float g_qbuf[(size_t)BHN * SEQ * DQK];
__device__ float g_kbuf[(size_t)BHN * SEQ * DQK];
__device__ float g_vt  [(size_t)BHN * DV * SEQ];
__device__ float g_om  [(size_t)TOK * (NH*DV)];
__device__ float g_attn[(size_t)BHN * SEQ * SEQ];
__device__ float g_invf[32];

// ---------------- generic batched GEMM: C = alpha * A * B^T ----------------
#define GBM 128
#define GBN 128
#define GBK 16
#define GTM 8
#define GTN 8

__global__ __launch_bounds__(256) void gemm_nt(
    const float* __restrict__ A, long lda, long sA,
    const float* __restrict__ B, long ldb, long sB,
    float* __restrict__ C, long ldc, long sC, long sC2, int zdiv,
    int M, int N, int K, float alpha, int mode)
{
    const int z = blockIdx.z;
    const float* Ab = A + (size_t)z * sA;
    const float* Bb = B + (size_t)z * sB;
    float* Cb = C + (size_t)(z / zdiv) * sC + (size_t)(z % zdiv) * sC2;

    const int m0 = blockIdx.y * GBM;
    const int n0 = blockIdx.x * GBN;
    if (mode == 1 && n0 >= m0 + GBM) return;
    int Keff = K;
    if (mode == 2) Keff = min(K, m0 + GBM);

    __shared__ float As[GBK][GBM + 4];
    __shared__ float Bs[GBK][GBN + 4];

    const int tid = threadIdx.x;
    const int tx = tid & 15;
    const int ty = tid >> 4;
    const int lrow  = tid >> 2;
    const int lcol4 = (tid & 3) * 4;

    float acc[GTM][GTN];
#pragma unroll
    for (int i = 0; i < GTM; i++)
#pragma unroll
        for (int j = 0; j < GTN; j++) acc[i][j] = 0.f;

    for (int k0 = 0; k0 < Keff; k0 += GBK) {
#pragma unroll
        for (int r = 0; r < 2; r++) {
            int m = lrow + r * 64;
            float4 v = make_float4(0.f, 0.f, 0.f, 0.f);
            if (m0 + m < M)
                v = *reinterpret_cast<const float4*>(&Ab[(size_t)(m0 + m) * lda + k0 + lcol4]);
            As[lcol4 + 0][m] = v.x; As[lcol4 + 1][m] = v.y;
            As[lcol4 + 2][m] = v.z; As[lcol4 + 3][m] = v.w;
        }
#pragma unroll
        for (int r = 0; r < 2; r++) {
            int n = lrow + r * 64;
            float4 v = make_float4(0.f, 0.f, 0.f, 0.f);
            if (n0 + n < N)
                v = *reinterpret_cast<const float4*>(&Bb[(size_t)(n0 + n) * ldb + k0 + lcol4]);
            Bs[lcol4 + 0][n] = v.x; Bs[lcol4 + 1][n] = v.y;
            Bs[lcol4 + 2][n] = v.z; Bs[lcol4 + 3][n] = v.w;
        }
        __syncthreads();
#pragma unroll
        for (int kk = 0; kk < GBK; kk++) {
            float ra[GTM], rb[GTN];
#pragma unroll
            for (int i = 0; i < GTM; i++) ra[i] = As[kk][ty * GTM + i];
#pragma unroll
            for (int j = 0; j < GTN; j++) rb[j] = Bs[kk][tx * GTN + j];
#pragma unroll
            for (int i = 0; i < GTM; i++)
#pragma unroll
                for (int j = 0; j < GTN; j++) acc[i][j] += ra[i] * rb[j];
        }
        __syncthreads();
    }

#pragma unroll
    for (int i = 0; i < GTM; i++) {
        int m = m0 + ty * GTM + i;
        if (m >= M) continue;
#pragma unroll
        for (int j = 0; j < GTN; j++) {
            int n = n0 + tx * GTN + j;
            if (n < N) Cb[(size_t)m * ldc + n] = alpha * acc[i][j];
        }
    }
}

// ---------------- RMSNorm (row-wise) ----------------
__global__ __launch_bounds__(256) void rmsnorm_k(
    const float* __restrict__ in, long ldin,
    const float* __restrict__ w,
    float* __restrict__ out, long ldout, int D)
{
    const int row = blockIdx.x;
    const float* x = in + (size_t)row * ldin;
    float* o = out + (size_t)row * ldout;

    float s = 0.f;
    for (int i = threadIdx.x; i < D; i += 256) { float v = x[i]; s += v * v; }
    __shared__ float red[8];
#pragma unroll
    for (int off = 16; off; off >>= 1) s += __shfl_xor_sync(0xffffffffu, s, off);
    if ((threadIdx.x & 31) == 0) red[threadIdx.x >> 5] = s;
    __syncthreads();
    float tot = red[0]+red[1]+red[2]+red[3]+red[4]+red[5]+red[6]+red[7];
    const float inv = rsqrtf(tot / (float)D + 1e-6f);
    for (int i = threadIdx.x; i < D; i += 256) o[i] = w[i] * x[i] * inv;
}

// ---------------- RoPE table ----------------
__global__ void init_rope() {
    int j = threadIdx.x;
    if (j < 32)
        g_invf[j] = (float)exp(-((double)(2 * j) / 64.0) * log(10000.0));
}

// ---------------- fused RoPE pack: one block per (bh, s) ----------------
// qbuf/kbuf layout [bh][s][192]. Rotation computed pairwise by one thread,
// trig in double of the fp32-rounded angle (immune to fast-math sincosf).
__global__ __launch_bounds__(256) void rope_pack() {
    const int blk = blockIdx.x;          // bh*SEQ + s
    const int s  = blk % SEQ;
    const int bh = blk / SEQ;
    const int h = bh % NH, b = bh / NH;
    const long t = (long)b * SEQ + s;
    const int tid = threadIdx.x;

    float* qdst = g_qbuf + (size_t)blk * DQK;
    float* kdst = g_kbuf + (size_t)blk * DQK;
    const float* qsrc  = g_q  + t * (NH * DQK) + (long)h * DQK;
    const float* knsrc = g_kv + t * (NH * 256) + (long)h * 256;
    const float* krsrc = g_c  + t * (KVLORA + ROPE_D) + KVLORA;

    if (tid < 128) {
        qdst[tid] = qsrc[tid];
        kdst[tid] = knsrc[tid];
    } else if (tid < 160) {
        int jj = tid - 128;
        float ang = (float)s * g_invf[jj];
        float c = (float)cos((double)ang);
        float sn = (float)sin((double)ang);
        float x0 = qsrc[128 + 2 * jj];
        float x1 = qsrc[128 + 2 * jj + 1];
        qdst[128 + jj] = x0 * c - x1 * sn;   // deinterleaved first half
        qdst[160 + jj] = x1 * c + x0 * sn;   // deinterleaved second half
    } else if (tid < 192) {
        int jj = tid - 160;
        float ang = (float)s * g_invf[jj];
        float c = (float)cos((double)ang);
        float sn = (float)sin((double)ang);
        float x0 = krsrc[2 * jj];
        float x1 = krsrc[2 * jj + 1];
        kdst[128 + jj] = x0 * c - x1 * sn;
        kdst[160 + jj] = x1 * c + x0 * sn;
    }
}

// ---------------- V transpose (naive gather): vt[bh][d][s] = V[s][d] -----
__global__ __launch_bounds__(256) void vtrans() {
    long idx = (long)blockIdx.x * 256 + threadIdx.x;   // over BHN*DV*SEQ
    const long total = (long)BHN * DV * SEQ;
    if (idx >= total) return;
    int s = (int)(idx % SEQ);
    long r = idx / SEQ;
    int d = (int)(r % DV);
    int bh = (int)(r / DV);
    int h = bh % NH, b = bh / NH;
    g_vt[idx] = g_kv[((size_t)b * SEQ + s) * (NH * 256) + (long)h * 256 + 128 + d];
}

// ---------------- causal softmax, two-pass over global row ----------------
__global__ __launch_bounds__(256) void softmax_causal(float* __restrict__ attn) {
    const long r = blockIdx.x;               // bh*SEQ + q
    const int q = (int)(r % SEQ);
    float* row = attn + r * SEQ;
    const int L = q + 1;
    __shared__ float red[8];

    float mx = -3.4e38f;
    for (int k = threadIdx.x; k < L; k += 256) mx = fmaxf(mx, row[k]);
#pragma unroll
    for (int o = 16; o; o >>= 1) mx = fmaxf(mx, __shfl_xor_sync(0xffffffffu, mx, o));
    if ((threadIdx.x & 31) == 0) red[threadIdx.x >> 5] = mx;
    __syncthreads();
    mx = fmaxf(fmaxf(fmaxf(red[0], red[1]), fmaxf(red[2], red[3])),
               fmaxf(fmaxf(red[4], red[5]), fmaxf(red[6], red[7])));
    __syncthreads();

    float s = 0.f;
    for (int k = threadIdx.x; k < L; k += 256) s += expf(row[k] - mx);
#pragma unroll
    for (int o = 16; o; o >>= 1) s += __shfl_xor_sync(0xffffffffu, s, o);
    if ((threadIdx.x & 31) == 0) red[threadIdx.x >> 5] = s;
    __syncthreads();
    s = red[0]+red[1]+red[2]+red[3]+red[4]+red[5]+red[6]+red[7];
    const float inv = 1.f / s;

    for (int k = threadIdx.x; k < L; k += 256) row[k] = expf(row[k] - mx) * inv;
    for (int k = L + (int)threadIdx.x; k < SEQ; k += 256) row[k] = 0.f;
}

// ---------------- host launch ----------------
extern "C" void kernel_launch(void* const* d_in, const int* in_sizes, int n_in,
                              void* d_out, int out_size)
{
    // Bind inputs by element count (robust to metadata ordering).
    // hidden(8388608,f32) vs mask(8388608,bool) tie-broken by first occurrence.
    const float *hs = 0, *w_q_down = 0, *q_norm_w = 0, *w_q_up = 0;
    const float *w_kv_down = 0, *kv_norm_w = 0, *w_kv_up = 0, *w_out = 0;
    for (int i = 0; i < n_in; i++) {
        long n = in_sizes[i];
        const float* ptr = (const float*)d_in[i];
        if (n == 8388608)      { if (!hs) hs = ptr; /* second is mask: ignore */ }
        else if (n == 3145728) w_q_down = ptr;
        else if (n == 1536)    q_norm_w = ptr;
        else if (n == 4718592) w_q_up = ptr;
        else if (n == 1179648) w_kv_down = ptr;
        else if (n == 512)     kv_norm_w = ptr;
        else if (n == 2097152) w_kv_up = ptr;
        else if (n == 4194304) w_out = ptr;
        // 4096 = position_ids (implicit arange): ignored
    }

    float* out_final = (float*)d_out;

    void* p;
    cudaGetSymbolAddress(&p, g_q1);   float* q1   = (float*)p;
    cudaGetSymbolAddress(&p, g_q);    float* q    = (float*)p;
    cudaGetSymbolAddress(&p, g_c);    float* c    = (float*)p;
    cudaGetSymbolAddress(&p, g_ckvn); float* ckvn = (float*)p;
    cudaGetSymbolAddress(&p, g_kv);   float* kv   = (float*)p;
    cudaGetSymbolAddress(&p, g_qbuf); float* qb   = (float*)p;
    cudaGetSymbolAddress(&p, g_kbuf); float* kb   = (float*)p;
    cudaGetSymbolAddress(&p, g_vt);   float* vt   = (float*)p;
    cudaGetSymbolAddress(&p, g_om);   float* om   = (float*)p;
    cudaGetSymbolAddress(&p, g_attn); float* attn_scratch = (float*)p;

    const size_t need = (size_t)TOK * HID + (size_t)BHN * SEQ * SEQ;
    float* attn_out = ((size_t)out_size >= need)
                    ? (float*)d_out + (size_t)TOK * HID
                    : attn_scratch;

    const float qk_scale = 1.0f / sqrtf((float)DQK);

    init_rope<<<1, 32>>>();

    // q1 = hs @ w_q_down^T
    gemm_nt<<<dim3(QLORA/128, TOK/128, 1), 256>>>(
        hs, HID, 0, w_q_down, HID, 0, q1, QLORA, 0, 0, 1,
        TOK, QLORA, HID, 1.f, 0);
    rmsnorm_k<<<TOK, 256>>>(q1, QLORA, q_norm_w, q1, QLORA, QLORA);
    // q = q1 @ w_q_up^T
    gemm_nt<<<dim3((NH*DQK)/128, TOK/128, 1), 256>>>(
        q1, QLORA, 0, w_q_up, QLORA, 0, q, NH*DQK, 0, 0, 1,
        TOK, NH*DQK, QLORA, 1.f, 0);
    // c = hs @ w_kv_down^T
    gemm_nt<<<dim3((KVLORA+ROPE_D+127)/128, TOK/128, 1), 256>>>(
        hs, HID, 0, w_kv_down, HID, 0, c, KVLORA+ROPE_D, 0, 0, 1,
        TOK, KVLORA+ROPE_D, HID, 1.f, 0);
    rmsnorm_k<<<TOK, 256>>>(c, KVLORA+ROPE_D, kv_norm_w, ckvn, KVLORA, KVLORA);
    // kv = ckvn @ w_kv_up^T
    gemm_nt<<<dim3((NH*256)/128, TOK/128, 1), 256>>>(
        ckvn, KVLORA, 0, w_kv_up, KVLORA, 0, kv, NH*256, 0, 0, 1,
        TOK, NH*256, KVLORA, 1.f, 0);

    // RoPE pack of Q/K, V transpose
    rope_pack<<<BHN*SEQ, 256>>>();
    {
        long total = (long)BHN * DV * SEQ;
        vtrans<<<(int)((total + 255) / 256), 256>>>();
    }

    // scores: attn[bh] = scale * Qbh @ Kbh^T  (causal tile skip)
    gemm_nt<<<dim3(SEQ/128, SEQ/128, BHN), 256>>>(
        qb, DQK, (long)SEQ*DQK,
        kb, DQK, (long)SEQ*DQK,
        attn_out, SEQ, (long)SEQ*SEQ, 0, 1,
        SEQ, SEQ, DQK, qk_scale, 1);

    softmax_causal<<<BHN*SEQ, 256>>>(attn_out);

    // O[bh] = attn[bh] @ V[bh]  -> om[(b*S+s)][h*128+d]
    gemm_nt<<<dim3(DV/128, SEQ/128, BHN), 256>>>(
        attn_out, SEQ, (long)SEQ*SEQ,
        vt, SEQ, (long)DV*SEQ,
        om, NH*DV, (long)SEQ*NH*DV, DV, NH,
        SEQ, DV, SEQ, 1.f, 2);

    // out = om @ w_out^T
    gemm_nt<<<dim3(HID/128, TOK/128, 1), 256>>>(
        om, NH*DV, 0, w_out, NH*DV, 0, out_final, HID, 0, 0, 1,
        TOK, HID, NH*DV, 1.f, 0);
}

// round 8
// speedup vs baseline: 1.6934x; 1.6934x over previous
#include <cuda_runtime.h>
#include <cuda_bf16.h>
#include <math.h>

// ---------------- problem constants ----------------
#define BATCH 2
#define SEQ   2048
#define HID   2048
#define NH    16
#define DQK   192      // 128 nope + 64 rope
#define DV    128
#define QLORA 1536
#define KVLORA 512
#define ROPE_D 64
#define TOK   (BATCH*SEQ)          // 4096
#define BHN   (BATCH*NH)           // 32

// ---------------- scratch (device globals; no runtime alloc) -------------
__device__ float g_q1  [(size_t)TOK * QLORA];
__device__ float g_q   [(size_t)TOK * (NH*DQK)];
__device__ float g_c   [(size_t)TOK * (KVLORA+ROPE_D)];
__device__ float g_ckvn[(size_t)TOK * KVLORA];
__device__ float g_kv  [(size_t)TOK * (NH*256)];
__device__ float g_qbuf[(size_t)BHN * SEQ * DQK];
__device__ float g_kbuf[(size_t)BHN * SEQ * DQK];
__device__ float g_vt  [(size_t)BHN * DV * SEQ];
__device__ float g_om  [(size_t)TOK * (NH*DV)];
__device__ float g_attn[(size_t)BHN * SEQ * SEQ];
__device__ float g_invf[32];

// ---------------- packed f32x2 helpers (FFMA2: PTX-only pattern) ----------
#define FMA_F32X2(d, a, b, c) \
    asm("fma.rn.f32x2 %0, %1, %2, %3;" : "=l"(d) : "l"(a), "l"(b), "l"(c))
#define BCAST_F32X2(d, f) \
    asm("mov.b64 %0, {%1, %1};" : "=l"(d) : "f"(f))
#define UNPACK_F32X2_(lo, hi, in) \
    asm("mov.b64 {%0, %1}, %2;" : "=f"(lo), "=f"(hi) : "l"(in))

// ---------------- generic batched GEMM: C = alpha * A * B^T ----------------
// A: [M,K] row-major (stride lda, batch stride sA)
// B: [N,K] row-major (stride ldb, batch stride sB)
// C: [M,N] row-major (stride ldc); batch base = C + (z/zdiv)*sC + (z%zdiv)*sC2
// mode 0: plain; 1: causal tile-skip; 2: K clamped to m0+BM
#define GBM 128
#define GBN 128
#define GBK 16
#define GTM 8
#define GTN 8

__global__ __launch_bounds__(256) void gemm_nt(
    const float* __restrict__ A, long lda, long sA,
    const float* __restrict__ B, long ldb, long sB,
    float* __restrict__ C, long ldc, long sC, long sC2, int zdiv,
    int M, int N, int K, float alpha, int mode)
{
    const int z = blockIdx.z;
    const float* Ab = A + (size_t)z * sA;
    const float* Bb = B + (size_t)z * sB;
    float* Cb = C + (size_t)(z / zdiv) * sC + (size_t)(z % zdiv) * sC2;

    const int m0 = blockIdx.y * GBM;
    const int n0 = blockIdx.x * GBN;
    if (mode == 1 && n0 >= m0 + GBM) return;
    int Keff = K;
    if (mode == 2) Keff = min(K, m0 + GBM);

    __shared__ float As[GBK][GBM + 4];
    __shared__ float Bs[GBK][GBN + 4];

    const int tid = threadIdx.x;
    const int tx = tid & 15;
    const int ty = tid >> 4;
    const int lrow  = tid >> 2;
    const int lcol4 = (tid & 3) * 4;

    // accumulators: 8 rows x 4 packed f32x2 column-pairs
    unsigned long long accp[GTM][GTN/2];
#pragma unroll
    for (int i = 0; i < GTM; i++)
#pragma unroll
        for (int j = 0; j < GTN/2; j++) accp[i][j] = 0ull;

    for (int k0 = 0; k0 < Keff; k0 += GBK) {
#pragma unroll
        for (int r = 0; r < 2; r++) {
            int m = lrow + r * 64;
            float4 v = make_float4(0.f, 0.f, 0.f, 0.f);
            if (m0 + m < M)
                v = *reinterpret_cast<const float4*>(&Ab[(size_t)(m0 + m) * lda + k0 + lcol4]);
            As[lcol4 + 0][m] = v.x; As[lcol4 + 1][m] = v.y;
            As[lcol4 + 2][m] = v.z; As[lcol4 + 3][m] = v.w;
        }
#pragma unroll
        for (int r = 0; r < 2; r++) {
            int n = lrow + r * 64;
            float4 v = make_float4(0.f, 0.f, 0.f, 0.f);
            if (n0 + n < N)
                v = *reinterpret_cast<const float4*>(&Bb[(size_t)(n0 + n) * ldb + k0 + lcol4]);
            Bs[lcol4 + 0][n] = v.x; Bs[lcol4 + 1][n] = v.y;
            Bs[lcol4 + 2][n] = v.z; Bs[lcol4 + 3][n] = v.w;
        }
        __syncthreads();
#pragma unroll
        for (int kk = 0; kk < GBK; kk++) {
            // rb: 8 consecutive floats = 4 aligned f32x2 pairs (free pairing via LDS.128)
            ulonglong2 b01 = *reinterpret_cast<const ulonglong2*>(&Bs[kk][tx * GTN]);
            ulonglong2 b23 = *reinterpret_cast<const ulonglong2*>(&Bs[kk][tx * GTN + 4]);
            unsigned long long bp[4] = { b01.x, b01.y, b23.x, b23.y };
            float4 a03 = *reinterpret_cast<const float4*>(&As[kk][ty * GTM]);
            float4 a47 = *reinterpret_cast<const float4*>(&As[kk][ty * GTM + 4]);
            float ra[GTM] = { a03.x, a03.y, a03.z, a03.w, a47.x, a47.y, a47.z, a47.w };
#pragma unroll
            for (int i = 0; i < GTM; i++) {
                unsigned long long ap;
                BCAST_F32X2(ap, ra[i]);
#pragma unroll
                for (int j = 0; j < GTN/2; j++)
                    FMA_F32X2(accp[i][j], ap, bp[j], accp[i][j]);
            }
        }
        __syncthreads();
    }

#pragma unroll
    for (int i = 0; i < GTM; i++) {
        int m = m0 + ty * GTM + i;
        if (m >= M) continue;
#pragma unroll
        for (int j = 0; j < GTN/2; j++) {
            float lo, hi;
            UNPACK_F32X2_(lo, hi, accp[i][j]);
            int n = n0 + tx * GTN + 2 * j;
            if (n < N)     Cb[(size_t)m * ldc + n]     = alpha * lo;
            if (n + 1 < N) Cb[(size_t)m * ldc + n + 1] = alpha * hi;
        }
    }
}

// ---------------- RMSNorm (row-wise) ----------------
__global__ __launch_bounds__(256) void rmsnorm_k(
    const float* __restrict__ in, long ldin,
    const float* __restrict__ w,
    float* __restrict__ out, long ldout, int D)
{
    const int row = blockIdx.x;
    const float* x = in + (size_t)row * ldin;
    float* o = out + (size_t)row * ldout;

    float s = 0.f;
    for (int i = threadIdx.x; i < D; i += 256) { float v = x[i]; s += v * v; }
    __shared__ float red[8];
#pragma unroll
    for (int off = 16; off; off >>= 1) s += __shfl_xor_sync(0xffffffffu, s, off);
    if ((threadIdx.x & 31) == 0) red[threadIdx.x >> 5] = s;
    __syncthreads();
    float tot = red[0]+red[1]+red[2]+red[3]+red[4]+red[5]+red[6]+red[7];
    const float inv = rsqrtf(tot / (float)D + 1e-6f);
    for (int i = threadIdx.x; i < D; i += 256) o[i] = w[i] * x[i] * inv;
}

// ---------------- RoPE table ----------------
__global__ void init_rope() {
    int j = threadIdx.x;
    if (j < 32)
        g_invf[j] = (float)exp(-((double)(2 * j) / 64.0) * log(10000.0));
}

// ---------------- fused RoPE pack: one block per (bh, s) ----------------
__global__ __launch_bounds__(256) void rope_pack() {
    const int blk = blockIdx.x;          // bh*SEQ + s
    const int s  = blk % SEQ;
    const int bh = blk / SEQ;
    const int h = bh % NH, b = bh / NH;
    const long t = (long)b * SEQ + s;
    const int tid = threadIdx.x;

    float* qdst = g_qbuf + (size_t)blk * DQK;
    float* kdst = g_kbuf + (size_t)blk * DQK;
    const float* qsrc  = g_q  + t * (NH * DQK) + (long)h * DQK;
    const float* knsrc = g_kv + t * (NH * 256) + (long)h * 256;
    const float* krsrc = g_c  + t * (KVLORA + ROPE_D) + KVLORA;

    if (tid < 128) {
        qdst[tid] = qsrc[tid];
        kdst[tid] = knsrc[tid];
    } else if (tid < 160) {
        int jj = tid - 128;
        float ang = (float)s * g_invf[jj];
        float c = (float)cos((double)ang);
        float sn = (float)sin((double)ang);
        float x0 = qsrc[128 + 2 * jj];
        float x1 = qsrc[128 + 2 * jj + 1];
        qdst[128 + jj] = x0 * c - x1 * sn;
        qdst[160 + jj] = x1 * c + x0 * sn;
    } else if (tid < 192) {
        int jj = tid - 160;
        float ang = (float)s * g_invf[jj];
        float c = (float)cos((double)ang);
        float sn = (float)sin((double)ang);
        float x0 = krsrc[2 * jj];
        float x1 = krsrc[2 * jj + 1];
        kdst[128 + jj] = x0 * c - x1 * sn;
        kdst[160 + jj] = x1 * c + x0 * sn;
    }
}

// ---------------- V transpose (naive gather): vt[bh][d][s] = V[s][d] -----
__global__ __launch_bounds__(256) void vtrans() {
    long idx = (long)blockIdx.x * 256 + threadIdx.x;
    const long total = (long)BHN * DV * SEQ;
    if (idx >= total) return;
    int s = (int)(idx % SEQ);
    long r = idx / SEQ;
    int d = (int)(r % DV);
    int bh = (int)(r / DV);
    int h = bh % NH, b = bh / NH;
    g_vt[idx] = g_kv[((size_t)b * SEQ + s) * (NH * 256) + (long)h * 256 + 128 + d];
}

// ---------------- causal softmax, two-pass over global row ----------------
__global__ __launch_bounds__(256) void softmax_causal(float* __restrict__ attn) {
    const long r = blockIdx.x;               // bh*SEQ + q
    const int q = (int)(r % SEQ);
    float* row = attn + r * SEQ;
    const int L = q + 1;
    __shared__ float red[8];

    float mx = -3.4e38f;
    for (int k = threadIdx.x; k < L; k += 256) mx = fmaxf(mx, row[k]);
#pragma unroll
    for (int o = 16; o; o >>= 1) mx = fmaxf(mx, __shfl_xor_sync(0xffffffffu, mx, o));
    if ((threadIdx.x & 31) == 0) red[threadIdx.x >> 5] = mx;
    __syncthreads();
    mx = fmaxf(fmaxf(fmaxf(red[0], red[1]), fmaxf(red[2], red[3])),
               fmaxf(fmaxf(red[4], red[5]), fmaxf(red[6], red[7])));
    __syncthreads();

    float s = 0.f;
    for (int k = threadIdx.x; k < L; k += 256) s += expf(row[k] - mx);
#pragma unroll
    for (int o = 16; o; o >>= 1) s += __shfl_xor_sync(0xffffffffu, s, o);
    if ((threadIdx.x & 31) == 0) red[threadIdx.x >> 5] = s;
    __syncthreads();
    s = red[0]+red[1]+red[2]+red[3]+red[4]+red[5]+red[6]+red[7];
    const float inv = 1.f / s;

    for (int k = threadIdx.x; k < L; k += 256) row[k] = expf(row[k] - mx) * inv;
    for (int k = L + (int)threadIdx.x; k < SEQ; k += 256) row[k] = 0.f;
}

// ---------------- host launch ----------------
extern "C" void kernel_launch(void* const* d_in, const int* in_sizes, int n_in,
                              void* d_out, int out_size)
{
    // Bind inputs by element count (robust to metadata ordering).
    const float *hs = 0, *w_q_down = 0, *q_norm_w = 0, *w_q_up = 0;
    const float *w_kv_down = 0, *kv_norm_w = 0, *w_kv_up = 0, *w_out = 0;
    for (int i = 0; i < n_in; i++) {
        long n = in_sizes[i];
        const float* ptr = (const float*)d_in[i];
        if (n == 8388608)      { if (!hs) hs = ptr; }
        else if (n == 3145728) w_q_down = ptr;
        else if (n == 1536)    q_norm_w = ptr;
        else if (n == 4718592) w_q_up = ptr;
        else if (n == 1179648) w_kv_down = ptr;
        else if (n == 512)     kv_norm_w = ptr;
        else if (n == 2097152) w_kv_up = ptr;
        else if (n == 4194304) w_out = ptr;
    }

    float* out_final = (float*)d_out;

    void* p;
    cudaGetSymbolAddress(&p, g_q1);   float* q1   = (float*)p;
    cudaGetSymbolAddress(&p, g_q);    float* q    = (float*)p;
    cudaGetSymbolAddress(&p, g_c);    float* c    = (float*)p;
    cudaGetSymbolAddress(&p, g_ckvn); float* ckvn = (float*)p;
    cudaGetSymbolAddress(&p, g_kv);   float* kv   = (float*)p;
    cudaGetSymbolAddress(&p, g_qbuf); float* qb   = (float*)p;
    cudaGetSymbolAddress(&p, g_kbuf); float* kb   = (float*)p;
    cudaGetSymbolAddress(&p, g_vt);   float* vt   = (float*)p;
    cudaGetSymbolAddress(&p, g_om);   float* om   = (float*)p;
    cudaGetSymbolAddress(&p, g_attn); float* attn_scratch = (float*)p;

    const size_t need = (size_t)TOK * HID + (size_t)BHN * SEQ * SEQ;
    float* attn_out = ((size_t)out_size >= need)
                    ? (float*)d_out + (size_t)TOK * HID
                    : attn_scratch;

    const float qk_scale = 1.0f / sqrtf((float)DQK);

    init_rope<<<1, 32>>>();

    // q1 = hs @ w_q_down^T
    gemm_nt<<<dim3(QLORA/128, TOK/128, 1), 256>>>(
        hs, HID, 0, w_q_down, HID, 0, q1, QLORA, 0, 0, 1,
        TOK, QLORA, HID, 1.f, 0);
    rmsnorm_k<<<TOK, 256>>>(q1, QLORA, q_norm_w, q1, QLORA, QLORA);
    // q = q1 @ w_q_up^T
    gemm_nt<<<dim3((NH*DQK)/128, TOK/128, 1), 256>>>(
        q1, QLORA, 0, w_q_up, QLORA, 0, q, NH*DQK, 0, 0, 1,
        TOK, NH*DQK, QLORA, 1.f, 0);
    // c = hs @ w_kv_down^T
    gemm_nt<<<dim3((KVLORA+ROPE_D+127)/128, TOK/128, 1), 256>>>(
        hs, HID, 0, w_kv_down, HID, 0, c, KVLORA+ROPE_D, 0, 0, 1,
        TOK, KVLORA+ROPE_D, HID, 1.f, 0);
    rmsnorm_k<<<TOK, 256>>>(c, KVLORA+ROPE_D, kv_norm_w, ckvn, KVLORA, KVLORA);
    // kv = ckvn @ w_kv_up^T
    gemm_nt<<<dim3((NH*256)/128, TOK/128, 1), 256>>>(
        ckvn, KVLORA, 0, w_kv_up, KVLORA, 0, kv, NH*256, 0, 0, 1,
        TOK, NH*256, KVLORA, 1.f, 0);

    // RoPE pack of Q/K, V transpose
    rope_pack<<<BHN*SEQ, 256>>>();
    {
        long total = (long)BHN * DV * SEQ;
        vtrans<<<(int)((total + 255) / 256), 256>>>();
    }

    // scores: attn[bh] = scale * Qbh @ Kbh^T  (causal tile skip)
    gemm_nt<<<dim3(SEQ/128, SEQ/128, BHN), 256>>>(
        qb, DQK, (long)SEQ*DQK,
        kb, DQK, (long)SEQ*DQK,
        attn_out, SEQ, (long)SEQ*SEQ, 0, 1,
        SEQ, SEQ, DQK, qk_scale, 1);

    softmax_causal<<<BHN*SEQ, 256>>>(attn_out);

    // O[bh] = attn[bh] @ V[bh]  -> om[(b*S+s)][h*128+d]
    gemm_nt<<<dim3(DV/128, SEQ/128, BHN), 256>>>(
        attn_out, SEQ, (long)SEQ*SEQ,
        vt, SEQ, (long)DV*SEQ,
        om, NH*DV, (long)SEQ*NH*DV, DV, NH,
        SEQ, DV, SEQ, 1.f, 2);

    // out = om @ w_out^T
    gemm_nt<<<dim3(HID/128, TOK/128, 1), 256>>>(
        om, NH*DV, 0, w_out, NH*DV, 0, out_final, HID, 0, 0, 1,
        TOK, HID, NH*DV, 1.f, 0);
}

// round 10
// speedup vs baseline: 2.7896x; 1.6474x over previous
#include <cuda_runtime.h>
#include <cuda_bf16.h>
#include <math.h>
#include <stdint.h>

// ---------------- problem constants ----------------
#define BATCH 2
#define SEQ   2048
#define HID   2048
#define NH    16
#define DQK   192
#define DV    128
#define QLORA 1536
#define KVLORA 512
#define ROPE_D 64
#define TOK   (BATCH*SEQ)          // 4096
#define BHN   (BATCH*NH)           // 32

// ---------------- fp32 scratch ----------------
__device__ float g_q1  [(size_t)TOK * QLORA];
__device__ float g_q   [(size_t)TOK * (NH*DQK)];
__device__ float g_c   [(size_t)TOK * (KVLORA+ROPE_D)];
__device__ float g_ckvn[(size_t)TOK * KVLORA];
__device__ float g_kv  [(size_t)TOK * (NH*256)];
__device__ float g_qbuf[(size_t)BHN * SEQ * DQK];
__device__ float g_kbuf[(size_t)BHN * SEQ * DQK];
__device__ float g_vt  [(size_t)BHN * DV * SEQ];
__device__ float g_om  [(size_t)TOK * (NH*DV)];
__device__ float g_attn[(size_t)BHN * SEQ * SEQ];
__device__ float g_invf[32];

// ---------------- bf16 split buffers (hi/lo) ----------------
__device__ __nv_bfloat16 b_hs_h [(size_t)TOK*HID],      b_hs_l [(size_t)TOK*HID];
__device__ __nv_bfloat16 b_wqd_h[(size_t)QLORA*HID],    b_wqd_l[(size_t)QLORA*HID];
__device__ __nv_bfloat16 b_wqu_h[(size_t)(NH*DQK)*QLORA], b_wqu_l[(size_t)(NH*DQK)*QLORA];
__device__ __nv_bfloat16 b_wkd_h[(size_t)(KVLORA+ROPE_D)*HID], b_wkd_l[(size_t)(KVLORA+ROPE_D)*HID];
__device__ __nv_bfloat16 b_wku_h[(size_t)(NH*256)*KVLORA], b_wku_l[(size_t)(NH*256)*KVLORA];
__device__ __nv_bfloat16 b_wo_h [(size_t)HID*(NH*DV)],  b_wo_l [(size_t)HID*(NH*DV)];
__device__ __nv_bfloat16 b_q1_h [(size_t)TOK*QLORA],    b_q1_l [(size_t)TOK*QLORA];
__device__ __nv_bfloat16 b_ck_h [(size_t)TOK*KVLORA],   b_ck_l [(size_t)TOK*KVLORA];
__device__ __nv_bfloat16 b_om_h [(size_t)TOK*(NH*DV)],  b_om_l [(size_t)TOK*(NH*DV)];

// ================= mma.sync helpers (sm_80+ PTX; valid for plain sm_103) ===
__device__ __forceinline__ uint32_t smem_u32(const void* p) {
    uint32_t a;
    asm("{ .reg .u64 t; cvta.to.shared.u64 t, %1; cvt.u32.u64 %0, t; }" : "=r"(a) : "l"(p));
    return a;
}
__device__ __forceinline__ void ldmx4(uint32_t* r, uint32_t addr) {
    asm volatile("ldmatrix.sync.aligned.m8n8.x4.shared.b16 {%0,%1,%2,%3}, [%4];"
        : "=r"(r[0]), "=r"(r[1]), "=r"(r[2]), "=r"(r[3]) : "r"(addr));
}
__device__ __forceinline__ void mma_bf16(float* d, const uint32_t* a, const uint32_t* b) {
    asm volatile("mma.sync.aligned.m16n8k16.row.col.f32.bf16.bf16.f32 "
        "{%0,%1,%2,%3}, {%4,%5,%6,%7}, {%8,%9}, {%0,%1,%2,%3};"
        : "+f"(d[0]), "+f"(d[1]), "+f"(d[2]), "+f"(d[3])
        : "r"(a[0]), "r"(a[1]), "r"(a[2]), "r"(a[3]), "r"(b[0]), "r"(b[1]));
}

// ---------------- mma_gemm: C[M,N] = Ah·Bh^T + Ah·Bl^T + Al·Bh^T (fp32) ----
// A*: [M,K] bf16 row-major, B*: [N,K] bf16 row-major. M%128==0, K%32==0.
// Block 128x128x32, 256 threads = 8 warps in 2x4 grid, warp tile 64x32.
#define TSTR 40   // smem row stride in bf16 (32 data + 8 pad -> conflict-free ldmatrix)

__global__ __launch_bounds__(256, 2) void mma_gemm(
    const __nv_bfloat16* __restrict__ Ah, const __nv_bfloat16* __restrict__ Al,
    const __nv_bfloat16* __restrict__ Bh, const __nv_bfloat16* __restrict__ Bl,
    float* __restrict__ C, int M, int N, int K)
{
    __shared__ __nv_bfloat16 sAh[128*TSTR], sAl[128*TSTR];
    __shared__ __nv_bfloat16 sBh[128*TSTR], sBl[128*TSTR];

    const int tid = threadIdx.x;
    const int lane = tid & 31;
    const int wid = tid >> 5;
    const int wm = wid >> 2;          // 0..1
    const int wn = wid & 3;           // 0..3
    const int m0 = blockIdx.y * 128, n0 = blockIdx.x * 128;

    float acc[4][4][4];
#pragma unroll
    for (int i = 0; i < 4; i++)
#pragma unroll
        for (int j = 0; j < 4; j++)
#pragma unroll
            for (int f = 0; f < 4; f++) acc[i][j][f] = 0.f;

    const uint32_t aH = smem_u32(sAh), aL = smem_u32(sAl);
    const uint32_t bH = smem_u32(sBh), bL = smem_u32(sBl);

    // ldmatrix lane address components
    const int a_row = wm * 64 + (lane & 15);
    const int a_col = ((lane >> 4) & 1) * 8;
    const int b_row = wn * 32 + ((lane >> 4) & 1) * 8 + (lane & 7);
    const int b_col = ((lane >> 3) & 1) * 8;

    // global load assignment: 512 16B-chunks per buffer, 2 per thread
    const int r0c = tid >> 2, c0 = (tid & 3) * 8;          // chunk tid
    const int r1c = (tid + 256) >> 2, c1 = ((tid + 256) & 3) * 8;

    for (int k0 = 0; k0 < K; k0 += 32) {
        {
            const size_t a0o = (size_t)(m0 + r0c) * K + k0 + c0;
            const size_t a1o = (size_t)(m0 + r1c) * K + k0 + c1;
            *(uint4*)&sAh[r0c * TSTR + c0] = *(const uint4*)(Ah + a0o);
            *(uint4*)&sAl[r0c * TSTR + c0] = *(const uint4*)(Al + a0o);
            *(uint4*)&sAh[r1c * TSTR + c1] = *(const uint4*)(Ah + a1o);
            *(uint4*)&sAl[r1c * TSTR + c1] = *(const uint4*)(Al + a1o);
            uint4 z = make_uint4(0,0,0,0);
            uint4 v0h = z, v0l = z, v1h = z, v1l = z;
            if (n0 + r0c < N) {
                const size_t o = (size_t)(n0 + r0c) * K + k0 + c0;
                v0h = *(const uint4*)(Bh + o); v0l = *(const uint4*)(Bl + o);
            }
            if (n0 + r1c < N) {
                const size_t o = (size_t)(n0 + r1c) * K + k0 + c1;
                v1h = *(const uint4*)(Bh + o); v1l = *(const uint4*)(Bl + o);
            }
            *(uint4*)&sBh[r0c * TSTR + c0] = v0h;
            *(uint4*)&sBl[r0c * TSTR + c0] = v0l;
            *(uint4*)&sBh[r1c * TSTR + c1] = v1h;
            *(uint4*)&sBl[r1c * TSTR + c1] = v1l;
        }
        __syncthreads();

#pragma unroll
        for (int k16 = 0; k16 < 2; k16++) {
            const int kc = k16 * 16;
            uint32_t bh[4][2], bl[4][2], af[4][4];
            // B hi/lo: 2 x4-ldmatrix each (each covers two n8 tiles)
#pragma unroll
            for (int g = 0; g < 2; g++) {
                uint32_t r[4];
                uint32_t off = ((b_row + g * 16) * TSTR + kc + b_col) * 2;
                ldmx4(r, bH + off);
                bh[2*g][0] = r[0]; bh[2*g][1] = r[1];
                bh[2*g+1][0] = r[2]; bh[2*g+1][1] = r[3];
                ldmx4(r, bL + off);
                bl[2*g][0] = r[0]; bl[2*g][1] = r[1];
                bl[2*g+1][0] = r[2]; bl[2*g+1][1] = r[3];
            }
            // A hi
#pragma unroll
            for (int mi = 0; mi < 4; mi++)
                ldmx4(af[mi], aH + ((a_row + mi * 16) * TSTR + kc + a_col) * 2);
            // pass 1+2: Ah*Bh, Ah*Bl
#pragma unroll
            for (int mi = 0; mi < 4; mi++)
#pragma unroll
                for (int nj = 0; nj < 4; nj++) {
                    mma_bf16(acc[mi][nj], af[mi], bh[nj]);
                    mma_bf16(acc[mi][nj], af[mi], bl[nj]);
                }
            // A lo (overwrite)
#pragma unroll
            for (int mi = 0; mi < 4; mi++)
                ldmx4(af[mi], aL + ((a_row + mi * 16) * TSTR + kc + a_col) * 2);
            // pass 3: Al*Bh
#pragma unroll
            for (int mi = 0; mi < 4; mi++)
#pragma unroll
                for (int nj = 0; nj < 4; nj++)
                    mma_bf16(acc[mi][nj], af[mi], bh[nj]);
        }
        __syncthreads();
    }

    // epilogue
#pragma unroll
    for (int mi = 0; mi < 4; mi++) {
        const int m1 = m0 + wm * 64 + mi * 16 + (lane >> 2);
        const int m2 = m1 + 8;
#pragma unroll
        for (int nj = 0; nj < 4; nj++) {
            const int n = n0 + wn * 32 + nj * 8 + (lane & 3) * 2;
            if (n < N) {
                *(float2*)&C[(size_t)m1 * N + n] = make_float2(acc[mi][nj][0], acc[mi][nj][1]);
                *(float2*)&C[(size_t)m2 * N + n] = make_float2(acc[mi][nj][2], acc[mi][nj][3]);
            }
        }
    }
}

// ---------------- fp32 -> (hi, lo) bf16 splitter ----------------
__global__ __launch_bounds__(256) void split_bf16(
    const float* __restrict__ x, __nv_bfloat16* __restrict__ h,
    __nv_bfloat16* __restrict__ l, long n)
{
    long i = (long)blockIdx.x * 256 + threadIdx.x;
    if (i >= n) return;
    float v = x[i];
    __nv_bfloat16 hi = __float2bfloat16(v);
    h[i] = hi;
    l[i] = __float2bfloat16(v - __bfloat162float(hi));
}

// ---------------- packed f32x2 helpers (FFMA2) ----------
#define FMA_F32X2(d, a, b, c) \
    asm("fma.rn.f32x2 %0, %1, %2, %3;" : "=l"(d) : "l"(a), "l"(b), "l"(c))
#define BCAST_F32X2(d, f) \
    asm("mov.b64 %0, {%1, %1};" : "=l"(d) : "f"(f))
#define UNPACK_F32X2_(lo, hi, in) \
    asm("mov.b64 {%0, %1}, %2;" : "=f"(lo), "=f"(hi) : "l"(in))

// ---------------- SIMT batched GEMM (attention): C = alpha * A * B^T ------
#define GBM 128
#define GBN 128
#define GBK 16
#define GTM 8
#define GTN 8

__global__ __launch_bounds__(256) void gemm_nt(
    const float* __restrict__ A, long lda, long sA,
    const float* __restrict__ B, long ldb, long sB,
    float* __restrict__ C, long ldc, long sC, long sC2, int zdiv,
    int M, int N, int K, float alpha, int mode)
{
    const int z = blockIdx.z;
    const float* Ab = A + (size_t)z * sA;
    const float* Bb = B + (size_t)z * sB;
    float* Cb = C + (size_t)(z / zdiv) * sC + (size_t)(z % zdiv) * sC2;

    const int m0 = blockIdx.y * GBM;
    const int n0 = blockIdx.x * GBN;
    if (mode == 1 && n0 >= m0 + GBM) return;
    int Keff = K;
    if (mode == 2) Keff = min(K, m0 + GBM);

    __shared__ float As[GBK][GBM + 4];
    __shared__ float Bs[GBK][GBN + 4];

    const int tid = threadIdx.x;
    const int tx = tid & 15;
    const int ty = tid >> 4;
    const int lrow  = tid >> 2;
    const int lcol4 = (tid & 3) * 4;

    unsigned long long accp[GTM][GTN/2];
#pragma unroll
    for (int i = 0; i < GTM; i++)
#pragma unroll
        for (int j = 0; j < GTN/2; j++) accp[i][j] = 0ull;

    for (int k0 = 0; k0 < Keff; k0 += GBK) {
#pragma unroll
        for (int r = 0; r < 2; r++) {
            int m = lrow + r * 64;
            float4 v = make_float4(0.f, 0.f, 0.f, 0.f);
            if (m0 + m < M)
                v = *reinterpret_cast<const float4*>(&Ab[(size_t)(m0 + m) * lda + k0 + lcol4]);
            As[lcol4 + 0][m] = v.x; As[lcol4 + 1][m] = v.y;
            As[lcol4 + 2][m] = v.z; As[lcol4 + 3][m] = v.w;
        }
#pragma unroll
        for (int r = 0; r < 2; r++) {
            int n = lrow + r * 64;
            float4 v = make_float4(0.f, 0.f, 0.f, 0.f);
            if (n0 + n < N)
                v = *reinterpret_cast<const float4*>(&Bb[(size_t)(n0 + n) * ldb + k0 + lcol4]);
            Bs[lcol4 + 0][n] = v.x; Bs[lcol4 + 1][n] = v.y;
            Bs[lcol4 + 2][n] = v.z; Bs[lcol4 + 3][n] = v.w;
        }
        __syncthreads();
#pragma unroll
        for (int kk = 0; kk < GBK; kk++) {
            ulonglong2 b01 = *reinterpret_cast<const ulonglong2*>(&Bs[kk][tx * GTN]);
            ulonglong2 b23 = *reinterpret_cast<const ulonglong2*>(&Bs[kk][tx * GTN + 4]);
            unsigned long long bp[4] = { b01.x, b01.y, b23.x, b23.y };
            float4 a03 = *reinterpret_cast<const float4*>(&As[kk][ty * GTM]);
            float4 a47 = *reinterpret_cast<const float4*>(&As[kk][ty * GTM + 4]);
            float ra[GTM] = { a03.x, a03.y, a03.z, a03.w, a47.x, a47.y, a47.z, a47.w };
#pragma unroll
            for (int i = 0; i < GTM; i++) {
                unsigned long long ap;
                BCAST_F32X2(ap, ra[i]);
#pragma unroll
                for (int j = 0; j < GTN/2; j++)
                    FMA_F32X2(accp[i][j], ap, bp[j], accp[i][j]);
            }
        }
        __syncthreads();
    }

#pragma unroll
    for (int i = 0; i < GTM; i++) {
        int m = m0 + ty * GTM + i;
        if (m >= M) continue;
#pragma unroll
        for (int j = 0; j < GTN/2; j++) {
            float lo, hi;
            UNPACK_F32X2_(lo, hi, accp[i][j]);
            int n = n0 + tx * GTN + 2 * j;
            if (n < N)     Cb[(size_t)m * ldc + n]     = alpha * lo;
            if (n + 1 < N) Cb[(size_t)m * ldc + n + 1] = alpha * hi;
        }
    }
}

// ---------------- RMSNorm ----------------
__global__ __launch_bounds__(256) void rmsnorm_k(
    const float* __restrict__ in, long ldin,
    const float* __restrict__ w,
    float* __restrict__ out, long ldout, int D)
{
    const int row = blockIdx.x;
    const float* x = in + (size_t)row * ldin;
    float* o = out + (size_t)row * ldout;

    float s = 0.f;
    for (int i = threadIdx.x; i < D; i += 256) { float v = x[i]; s += v * v; }
    __shared__ float red[8];
#pragma unroll
    for (int off = 16; off; off >>= 1) s += __shfl_xor_sync(0xffffffffu, s, off);
    if ((threadIdx.x & 31) == 0) red[threadIdx.x >> 5] = s;
    __syncthreads();
    float tot = red[0]+red[1]+red[2]+red[3]+red[4]+red[5]+red[6]+red[7];
    const float inv = rsqrtf(tot / (float)D + 1e-6f);
    for (int i = threadIdx.x; i < D; i += 256) o[i] = w[i] * x[i] * inv;
}

// ---------------- RoPE table ----------------
__global__ void init_rope() {
    int j = threadIdx.x;
    if (j < 32)
        g_invf[j] = (float)exp(-((double)(2 * j) / 64.0) * log(10000.0));
}

// ---------------- fused RoPE pack ----------------
__global__ __launch_bounds__(256) void rope_pack() {
    const int blk = blockIdx.x;
    const int s  = blk % SEQ;
    const int bh = blk / SEQ;
    const int h = bh % NH, b = bh / NH;
    const long t = (long)b * SEQ + s;
    const int tid = threadIdx.x;

    float* qdst = g_qbuf + (size_t)blk * DQK;
    float* kdst = g_kbuf + (size_t)blk * DQK;
    const float* qsrc  = g_q  + t * (NH * DQK) + (long)h * DQK;
    const float* knsrc = g_kv + t * (NH * 256) + (long)h * 256;
    const float* krsrc = g_c  + t * (KVLORA + ROPE_D) + KVLORA;

    if (tid < 128) {
        qdst[tid] = qsrc[tid];
        kdst[tid] = knsrc[tid];
    } else if (tid < 160) {
        int jj = tid - 128;
        float ang = (float)s * g_invf[jj];
        float c = (float)cos((double)ang);
        float sn = (float)sin((double)ang);
        float x0 = qsrc[128 + 2 * jj];
        float x1 = qsrc[128 + 2 * jj + 1];
        qdst[128 + jj] = x0 * c - x1 * sn;
        qdst[160 + jj] = x1 * c + x0 * sn;
    } else if (tid < 192) {
        int jj = tid - 160;
        float ang = (float)s * g_invf[jj];
        float c = (float)cos((double)ang);
        float sn = (float)sin((double)ang);
        float x0 = krsrc[2 * jj];
        float x1 = krsrc[2 * jj + 1];
        kdst[128 + jj] = x0 * c - x1 * sn;
        kdst[160 + jj] = x1 * c + x0 * sn;
    }
}

// ---------------- V transpose ----------------
__global__ __launch_bounds__(256) void vtrans() {
    long idx = (long)blockIdx.x * 256 + threadIdx.x;
    const long total = (long)BHN * DV * SEQ;
    if (idx >= total) return;
    int s = (int)(idx % SEQ);
    long r = idx / SEQ;
    int d = (int)(r % DV);
    int bh = (int)(r / DV);
    int h = bh % NH, b = bh / NH;
    g_vt[idx] = g_kv[((size_t)b * SEQ + s) * (NH * 256) + (long)h * 256 + 128 + d];
}

// ---------------- causal softmax ----------------
__global__ __launch_bounds__(256) void softmax_causal(float* __restrict__ attn) {
    const long r = blockIdx.x;
    const int q = (int)(r % SEQ);
    float* row = attn + r * SEQ;
    const int L = q + 1;
    __shared__ float red[8];

    float mx = -3.4e38f;
    for (int k = threadIdx.x; k < L; k += 256) mx = fmaxf(mx, row[k]);
#pragma unroll
    for (int o = 16; o; o >>= 1) mx = fmaxf(mx, __shfl_xor_sync(0xffffffffu, mx, o));
    if ((threadIdx.x & 31) == 0) red[threadIdx.x >> 5] = mx;
    __syncthreads();
    mx = fmaxf(fmaxf(fmaxf(red[0], red[1]), fmaxf(red[2], red[3])),
               fmaxf(fmaxf(red[4], red[5]), fmaxf(red[6], red[7])));
    __syncthreads();

    float s = 0.f;
    for (int k = threadIdx.x; k < L; k += 256) s += expf(row[k] - mx);
#pragma unroll
    for (int o = 16; o; o >>= 1) s += __shfl_xor_sync(0xffffffffu, s, o);
    if ((threadIdx.x & 31) == 0) red[threadIdx.x >> 5] = s;
    __syncthreads();
    s = red[0]+red[1]+red[2]+red[3]+red[4]+red[5]+red[6]+red[7];
    const float inv = 1.f / s;

    for (int k = threadIdx.x; k < L; k += 256) row[k] = expf(row[k] - mx) * inv;
    for (int k = L + (int)threadIdx.x; k < SEQ; k += 256) row[k] = 0.f;
}

// ---------------- host launch ----------------
static inline int cdiv(long a, long b) { return (int)((a + b - 1) / b); }

extern "C" void kernel_launch(void* const* d_in, const int* in_sizes, int n_in,
                              void* d_out, int out_size)
{
    const float *hs = 0, *w_q_down = 0, *q_norm_w = 0, *w_q_up = 0;
    const float *w_kv_down = 0, *kv_norm_w = 0, *w_kv_up = 0, *w_out = 0;
    for (int i = 0; i < n_in; i++) {
        long n = in_sizes[i];
        const float* ptr = (const float*)d_in[i];
        if (n == 8388608)      { if (!hs) hs = ptr; }
        else if (n == 3145728) w_q_down = ptr;
        else if (n == 1536)    q_norm_w = ptr;
        else if (n == 4718592) w_q_up = ptr;
        else if (n == 1179648) w_kv_down = ptr;
        else if (n == 512)     kv_norm_w = ptr;
        else if (n == 2097152) w_kv_up = ptr;
        else if (n == 4194304) w_out = ptr;
    }

    float* out_final = (float*)d_out;

    void* p;
    cudaGetSymbolAddress(&p, g_q1);   float* q1   = (float*)p;
    cudaGetSymbolAddress(&p, g_q);    float* q    = (float*)p;
    cudaGetSymbolAddress(&p, g_c);    float* c    = (float*)p;
    cudaGetSymbolAddress(&p, g_ckvn); float* ckvn = (float*)p;
    cudaGetSymbolAddress(&p, g_kv);   float* kv   = (float*)p;
    cudaGetSymbolAddress(&p, g_qbuf); float* qb   = (float*)p;
    cudaGetSymbolAddress(&p, g_kbuf); float* kb   = (float*)p;
    cudaGetSymbolAddress(&p, g_vt);   float* vt   = (float*)p;
    cudaGetSymbolAddress(&p, g_om);   float* om   = (float*)p;
    cudaGetSymbolAddress(&p, g_attn); float* attn_scratch = (float*)p;

    __nv_bfloat16 *hsh, *hsl, *wqdh, *wqdl, *wquh, *wqul, *wkdh, *wkdl, *wkuh, *wkul, *woh, *wol;
    __nv_bfloat16 *q1h, *q1l, *ckh, *ckl, *omh, *oml;
    cudaGetSymbolAddress(&p, b_hs_h);  hsh  = (__nv_bfloat16*)p;
    cudaGetSymbolAddress(&p, b_hs_l);  hsl  = (__nv_bfloat16*)p;
    cudaGetSymbolAddress(&p, b_wqd_h); wqdh = (__nv_bfloat16*)p;
    cudaGetSymbolAddress(&p, b_wqd_l); wqdl = (__nv_bfloat16*)p;
    cudaGetSymbolAddress(&p, b_wqu_h); wquh = (__nv_bfloat16*)p;
    cudaGetSymbolAddress(&p, b_wqu_l); wqul = (__nv_bfloat16*)p;
    cudaGetSymbolAddress(&p, b_wkd_h); wkdh = (__nv_bfloat16*)p;
    cudaGetSymbolAddress(&p, b_wkd_l); wkdl = (__nv_bfloat16*)p;
    cudaGetSymbolAddress(&p, b_wku_h); wkuh = (__nv_bfloat16*)p;
    cudaGetSymbolAddress(&p, b_wku_l); wkul = (__nv_bfloat16*)p;
    cudaGetSymbolAddress(&p, b_wo_h);  woh  = (__nv_bfloat16*)p;
    cudaGetSymbolAddress(&p, b_wo_l);  wol  = (__nv_bfloat16*)p;
    cudaGetSymbolAddress(&p, b_q1_h);  q1h  = (__nv_bfloat16*)p;
    cudaGetSymbolAddress(&p, b_q1_l);  q1l  = (__nv_bfloat16*)p;
    cudaGetSymbolAddress(&p, b_ck_h);  ckh  = (__nv_bfloat16*)p;
    cudaGetSymbolAddress(&p, b_ck_l);  ckl  = (__nv_bfloat16*)p;
    cudaGetSymbolAddress(&p, b_om_h);  omh  = (__nv_bfloat16*)p;
    cudaGetSymbolAddress(&p, b_om_l);  oml  = (__nv_bfloat16*)p;

    const size_t need = (size_t)TOK * HID + (size_t)BHN * SEQ * SEQ;
    float* attn_out = ((size_t)out_size >= need)
                    ? (float*)d_out + (size_t)TOK * HID
                    : attn_scratch;

    const float qk_scale = 1.0f / sqrtf((float)DQK);

    init_rope<<<1, 32>>>();

    // split inputs + weights to bf16 hi/lo
    { long n = (long)TOK*HID;              split_bf16<<<cdiv(n,256),256>>>(hs, hsh, hsl, n); }
    { long n = (long)QLORA*HID;            split_bf16<<<cdiv(n,256),256>>>(w_q_down, wqdh, wqdl, n); }
    { long n = (long)(NH*DQK)*QLORA;       split_bf16<<<cdiv(n,256),256>>>(w_q_up, wquh, wqul, n); }
    { long n = (long)(KVLORA+ROPE_D)*HID;  split_bf16<<<cdiv(n,256),256>>>(w_kv_down, wkdh, wkdl, n); }
    { long n = (long)(NH*256)*KVLORA;      split_bf16<<<cdiv(n,256),256>>>(w_kv_up, wkuh, wkul, n); }
    { long n = (long)HID*(NH*DV);          split_bf16<<<cdiv(n,256),256>>>(w_out, woh, wol, n); }

    // q1 = hs @ w_q_down^T  [4096 x 1536], K=2048
    mma_gemm<<<dim3(QLORA/128, TOK/128), 256>>>(hsh, hsl, wqdh, wqdl, q1, TOK, QLORA, HID);
    rmsnorm_k<<<TOK, 256>>>(q1, QLORA, q_norm_w, q1, QLORA, QLORA);
    { long n = (long)TOK*QLORA; split_bf16<<<cdiv(n,256),256>>>(q1, q1h, q1l, n); }

    // q = q1n @ w_q_up^T  [4096 x 3072], K=1536
    mma_gemm<<<dim3((NH*DQK)/128, TOK/128), 256>>>(q1h, q1l, wquh, wqul, q, TOK, NH*DQK, QLORA);

    // c = hs @ w_kv_down^T  [4096 x 576], K=2048
    mma_gemm<<<dim3(cdiv(KVLORA+ROPE_D,128), TOK/128), 256>>>(hsh, hsl, wkdh, wkdl, c, TOK, KVLORA+ROPE_D, HID);
    rmsnorm_k<<<TOK, 256>>>(c, KVLORA+ROPE_D, kv_norm_w, ckvn, KVLORA, KVLORA);
    { long n = (long)TOK*KVLORA; split_bf16<<<cdiv(n,256),256>>>(ckvn, ckh, ckl, n); }

    // kv = ckvn @ w_kv_up^T  [4096 x 4096], K=512
    mma_gemm<<<dim3((NH*256)/128, TOK/128), 256>>>(ckh, ckl, wkuh, wkul, kv, TOK, NH*256, KVLORA);

    // RoPE pack of Q/K, V transpose
    rope_pack<<<BHN*SEQ, 256>>>();
    {
        long total = (long)BHN * DV * SEQ;
        vtrans<<<(int)((total + 255) / 256), 256>>>();
    }

    // scores (causal tile skip) — SIMT FFMA2
    gemm_nt<<<dim3(SEQ/128, SEQ/128, BHN), 256>>>(
        qb, DQK, (long)SEQ*DQK,
        kb, DQK, (long)SEQ*DQK,
        attn_out, SEQ, (long)SEQ*SEQ, 0, 1,
        SEQ, SEQ, DQK, qk_scale, 1);

    softmax_causal<<<BHN*SEQ, 256>>>(attn_out);

    // O = attn @ V — SIMT FFMA2 (K clamped causally)
    gemm_nt<<<dim3(DV/128, SEQ/128, BHN), 256>>>(
        attn_out, SEQ, (long)SEQ*SEQ,
        vt, SEQ, (long)DV*SEQ,
        om, NH*DV, (long)SEQ*NH*DV, DV, NH,
        SEQ, DV, SEQ, 1.f, 2);

    // out = om @ w_out^T  [4096 x 2048], K=2048
    { long n = (long)TOK*(NH*DV); split_bf16<<<cdiv(n,256),256>>>(om, omh, oml, n); }
    mma_gemm<<<dim3(HID/128, TOK/128), 256>>>(omh, oml, woh, wol, out_final, TOK, HID, NH*DV);
}

// round 11
// speedup vs baseline: 3.5454x; 1.2709x over previous
#include <cuda_runtime.h>
#include <cuda_bf16.h>
#include <math.h>
#include <stdint.h>

// ---------------- problem constants ----------------
#define BATCH 2
#define SEQ   2048
#define HID   2048
#define NH    16
#define DQK   192
#define DV    128
#define QLORA 1536
#define KVLORA 512
#define ROPE_D 64
#define TOK   (BATCH*SEQ)          // 4096
#define BHN   (BATCH*NH)           // 32

// ---------------- fp32 scratch ----------------
__device__ float g_q1  [(size_t)TOK * QLORA];
__device__ float g_q   [(size_t)TOK * (NH*DQK)];
__device__ float g_c   [(size_t)TOK * (KVLORA+ROPE_D)];
__device__ float g_ckvn[(size_t)TOK * KVLORA];
__device__ float g_kv  [(size_t)TOK * (NH*256)];
__device__ float g_qbuf[(size_t)BHN * SEQ * DQK];
__device__ float g_kbuf[(size_t)BHN * SEQ * DQK];
__device__ float g_vt  [(size_t)BHN * DV * SEQ];
__device__ float g_om  [(size_t)TOK * (NH*DV)];
__device__ float g_attn[(size_t)BHN * SEQ * SEQ];
__device__ float g_invf[32];

// ---------------- bf16 split buffers (hi/lo) ----------------
__device__ __nv_bfloat16 b_hs_h [(size_t)TOK*HID],      b_hs_l [(size_t)TOK*HID];
__device__ __nv_bfloat16 b_wqd_h[(size_t)QLORA*HID],    b_wqd_l[(size_t)QLORA*HID];
__device__ __nv_bfloat16 b_wqu_h[(size_t)(NH*DQK)*QLORA], b_wqu_l[(size_t)(NH*DQK)*QLORA];
__device__ __nv_bfloat16 b_wkd_h[(size_t)(KVLORA+ROPE_D)*HID], b_wkd_l[(size_t)(KVLORA+ROPE_D)*HID];
__device__ __nv_bfloat16 b_wku_h[(size_t)(NH*256)*KVLORA], b_wku_l[(size_t)(NH*256)*KVLORA];
__device__ __nv_bfloat16 b_wo_h [(size_t)HID*(NH*DV)],  b_wo_l [(size_t)HID*(NH*DV)];
__device__ __nv_bfloat16 b_q1_h [(size_t)TOK*QLORA],    b_q1_l [(size_t)TOK*QLORA];
__device__ __nv_bfloat16 b_ck_h [(size_t)TOK*KVLORA],   b_ck_l [(size_t)TOK*KVLORA];
__device__ __nv_bfloat16 b_om_h [(size_t)TOK*(NH*DV)],  b_om_l [(size_t)TOK*(NH*DV)];
// attention-path bf16 buffers
__device__ __nv_bfloat16 b_qb_h [(size_t)BHN*SEQ*DQK],  b_qb_l [(size_t)BHN*SEQ*DQK];
__device__ __nv_bfloat16 b_kb_h [(size_t)BHN*SEQ*DQK],  b_kb_l [(size_t)BHN*SEQ*DQK];
__device__ __nv_bfloat16 b_vt_h [(size_t)BHN*DV*SEQ],   b_vt_l [(size_t)BHN*DV*SEQ];
__device__ __nv_bfloat16 b_at_h [(size_t)BHN*SEQ*SEQ],  b_at_l [(size_t)BHN*SEQ*SEQ];

// ================= mma.sync helpers =================
__device__ __forceinline__ uint32_t smem_u32(const void* p) {
    uint32_t a;
    asm("{ .reg .u64 t; cvta.to.shared.u64 t, %1; cvt.u32.u64 %0, t; }" : "=r"(a) : "l"(p));
    return a;
}
__device__ __forceinline__ void ldmx4(uint32_t* r, uint32_t addr) {
    asm volatile("ldmatrix.sync.aligned.m8n8.x4.shared.b16 {%0,%1,%2,%3}, [%4];"
        : "=r"(r[0]), "=r"(r[1]), "=r"(r[2]), "=r"(r[3]) : "r"(addr));
}
__device__ __forceinline__ void mma_bf16(float* d, const uint32_t* a, const uint32_t* b) {
    asm volatile("mma.sync.aligned.m16n8k16.row.col.f32.bf16.bf16.f32 "
        "{%0,%1,%2,%3}, {%4,%5,%6,%7}, {%8,%9}, {%0,%1,%2,%3};"
        : "+f"(d[0]), "+f"(d[1]), "+f"(d[2]), "+f"(d[3])
        : "r"(a[0]), "r"(a[1]), "r"(a[2]), "r"(a[3]), "r"(b[0]), "r"(b[1]));
}

// ---------------- batched split-bf16 tensor GEMM -------------------------
// C = alpha * (Ah+Al) * (Bh+Bl)^T  (3-pass compensation, fp32 accum)
// A*: [M,K] bf16, row stride lda, batch stride sA
// B*: [N,K] bf16, row stride ldb, batch stride sB
// C : fp32, row stride ldc; batch base = C + (z/zdiv)*sC + (z%zdiv)*sC2
// mode 0 plain; 1 causal tile-skip; 2 K clamped to m0+128.
// M%128==0, K%32==0 (also after mode-2 clamping).
#define TSTR 40   // smem row stride in bf16

__global__ __launch_bounds__(256, 2) void mma_gemm(
    const __nv_bfloat16* __restrict__ Ah, const __nv_bfloat16* __restrict__ Al,
    const __nv_bfloat16* __restrict__ Bh, const __nv_bfloat16* __restrict__ Bl,
    float* __restrict__ C,
    long lda, long sA, long ldb, long sB,
    long ldc, long sC, long sC2, int zdiv,
    int M, int N, int K, float alpha, int mode)
{
    __shared__ __nv_bfloat16 sAh[128*TSTR], sAl[128*TSTR];
    __shared__ __nv_bfloat16 sBh[128*TSTR], sBl[128*TSTR];

    const int z = blockIdx.z;
    const __nv_bfloat16* Abh = Ah + (size_t)z * sA;
    const __nv_bfloat16* Abl = Al + (size_t)z * sA;
    const __nv_bfloat16* Bbh = Bh + (size_t)z * sB;
    const __nv_bfloat16* Bbl = Bl + (size_t)z * sB;
    float* Cb = C + (size_t)(z / zdiv) * sC + (size_t)(z % zdiv) * sC2;

    const int tid = threadIdx.x;
    const int lane = tid & 31;
    const int wid = tid >> 5;
    const int wm = wid >> 2;          // 0..1
    const int wn = wid & 3;           // 0..3
    const int m0 = blockIdx.y * 128, n0 = blockIdx.x * 128;
    if (mode == 1 && n0 >= m0 + 128) return;
    int Keff = K;
    if (mode == 2) Keff = min(K, m0 + 128);

    float acc[4][4][4];
#pragma unroll
    for (int i = 0; i < 4; i++)
#pragma unroll
        for (int j = 0; j < 4; j++)
#pragma unroll
            for (int f = 0; f < 4; f++) acc[i][j][f] = 0.f;

    const uint32_t aH = smem_u32(sAh), aL = smem_u32(sAl);
    const uint32_t bH = smem_u32(sBh), bL = smem_u32(sBl);

    const int a_row = wm * 64 + (lane & 15);
    const int a_col = ((lane >> 4) & 1) * 8;
    const int b_row = wn * 32 + ((lane >> 4) & 1) * 8 + (lane & 7);
    const int b_col = ((lane >> 3) & 1) * 8;

    const int r0c = tid >> 2, c0 = (tid & 3) * 8;
    const int r1c = (tid + 256) >> 2, c1 = ((tid + 256) & 3) * 8;

    for (int k0 = 0; k0 < Keff; k0 += 32) {
        {
            const size_t a0o = (size_t)(m0 + r0c) * lda + k0 + c0;
            const size_t a1o = (size_t)(m0 + r1c) * lda + k0 + c1;
            *(uint4*)&sAh[r0c * TSTR + c0] = *(const uint4*)(Abh + a0o);
            *(uint4*)&sAl[r0c * TSTR + c0] = *(const uint4*)(Abl + a0o);
            *(uint4*)&sAh[r1c * TSTR + c1] = *(const uint4*)(Abh + a1o);
            *(uint4*)&sAl[r1c * TSTR + c1] = *(const uint4*)(Abl + a1o);
            uint4 z4 = make_uint4(0,0,0,0);
            uint4 v0h = z4, v0l = z4, v1h = z4, v1l = z4;
            if (n0 + r0c < N) {
                const size_t o = (size_t)(n0 + r0c) * ldb + k0 + c0;
                v0h = *(const uint4*)(Bbh + o); v0l = *(const uint4*)(Bbl + o);
            }
            if (n0 + r1c < N) {
                const size_t o = (size_t)(n0 + r1c) * ldb + k0 + c1;
                v1h = *(const uint4*)(Bbh + o); v1l = *(const uint4*)(Bbl + o);
            }
            *(uint4*)&sBh[r0c * TSTR + c0] = v0h;
            *(uint4*)&sBl[r0c * TSTR + c0] = v0l;
            *(uint4*)&sBh[r1c * TSTR + c1] = v1h;
            *(uint4*)&sBl[r1c * TSTR + c1] = v1l;
        }
        __syncthreads();

#pragma unroll
        for (int k16 = 0; k16 < 2; k16++) {
            const int kc = k16 * 16;
            uint32_t bh[4][2], bl[4][2], af[4][4];
#pragma unroll
            for (int g = 0; g < 2; g++) {
                uint32_t r[4];
                uint32_t off = ((b_row + g * 16) * TSTR + kc + b_col) * 2;
                ldmx4(r, bH + off);
                bh[2*g][0] = r[0]; bh[2*g][1] = r[1];
                bh[2*g+1][0] = r[2]; bh[2*g+1][1] = r[3];
                ldmx4(r, bL + off);
                bl[2*g][0] = r[0]; bl[2*g][1] = r[1];
                bl[2*g+1][0] = r[2]; bl[2*g+1][1] = r[3];
            }
#pragma unroll
            for (int mi = 0; mi < 4; mi++)
                ldmx4(af[mi], aH + ((a_row + mi * 16) * TSTR + kc + a_col) * 2);
#pragma unroll
            for (int mi = 0; mi < 4; mi++)
#pragma unroll
                for (int nj = 0; nj < 4; nj++) {
                    mma_bf16(acc[mi][nj], af[mi], bh[nj]);
                    mma_bf16(acc[mi][nj], af[mi], bl[nj]);
                }
#pragma unroll
            for (int mi = 0; mi < 4; mi++)
                ldmx4(af[mi], aL + ((a_row + mi * 16) * TSTR + kc + a_col) * 2);
#pragma unroll
            for (int mi = 0; mi < 4; mi++)
#pragma unroll
                for (int nj = 0; nj < 4; nj++)
                    mma_bf16(acc[mi][nj], af[mi], bh[nj]);
        }
        __syncthreads();
    }

#pragma unroll
    for (int mi = 0; mi < 4; mi++) {
        const int m1 = m0 + wm * 64 + mi * 16 + (lane >> 2);
        const int m2 = m1 + 8;
#pragma unroll
        for (int nj = 0; nj < 4; nj++) {
            const int n = n0 + wn * 32 + nj * 8 + (lane & 3) * 2;
            if (n < N) {
                *(float2*)&Cb[(size_t)m1 * ldc + n] =
                    make_float2(alpha * acc[mi][nj][0], alpha * acc[mi][nj][1]);
                *(float2*)&Cb[(size_t)m2 * ldc + n] =
                    make_float2(alpha * acc[mi][nj][2], alpha * acc[mi][nj][3]);
            }
        }
    }
}

// ---------------- fp32 -> (hi, lo) bf16 splitter ----------------
__global__ __launch_bounds__(256) void split_bf16(
    const float* __restrict__ x, __nv_bfloat16* __restrict__ h,
    __nv_bfloat16* __restrict__ l, long n)
{
    long i = (long)blockIdx.x * 256 + threadIdx.x;
    if (i >= n) return;
    float v = x[i];
    __nv_bfloat16 hi = __float2bfloat16(v);
    h[i] = hi;
    l[i] = __float2bfloat16(v - __bfloat162float(hi));
}

// ---------------- RMSNorm ----------------
__global__ __launch_bounds__(256) void rmsnorm_k(
    const float* __restrict__ in, long ldin,
    const float* __restrict__ w,
    float* __restrict__ out, long ldout, int D)
{
    const int row = blockIdx.x;
    const float* x = in + (size_t)row * ldin;
    float* o = out + (size_t)row * ldout;

    float s = 0.f;
    for (int i = threadIdx.x; i < D; i += 256) { float v = x[i]; s += v * v; }
    __shared__ float red[8];
#pragma unroll
    for (int off = 16; off; off >>= 1) s += __shfl_xor_sync(0xffffffffu, s, off);
    if ((threadIdx.x & 31) == 0) red[threadIdx.x >> 5] = s;
    __syncthreads();
    float tot = red[0]+red[1]+red[2]+red[3]+red[4]+red[5]+red[6]+red[7];
    const float inv = rsqrtf(tot / (float)D + 1e-6f);
    for (int i = threadIdx.x; i < D; i += 256) o[i] = w[i] * x[i] * inv;
}

// ---------------- RoPE table ----------------
__global__ void init_rope() {
    int j = threadIdx.x;
    if (j < 32)
        g_invf[j] = (float)exp(-((double)(2 * j) / 64.0) * log(10000.0));
}

// ---------------- fused RoPE pack ----------------
__global__ __launch_bounds__(256) void rope_pack() {
    const int blk = blockIdx.x;
    const int s  = blk % SEQ;
    const int bh = blk / SEQ;
    const int h = bh % NH, b = bh / NH;
    const long t = (long)b * SEQ + s;
    const int tid = threadIdx.x;

    float* qdst = g_qbuf + (size_t)blk * DQK;
    float* kdst = g_kbuf + (size_t)blk * DQK;
    const float* qsrc  = g_q  + t * (NH * DQK) + (long)h * DQK;
    const float* knsrc = g_kv + t * (NH * 256) + (long)h * 256;
    const float* krsrc = g_c  + t * (KVLORA + ROPE_D) + KVLORA;

    if (tid < 128) {
        qdst[tid] = qsrc[tid];
        kdst[tid] = knsrc[tid];
    } else if (tid < 160) {
        int jj = tid - 128;
        float ang = (float)s * g_invf[jj];
        float c = (float)cos((double)ang);
        float sn = (float)sin((double)ang);
        float x0 = qsrc[128 + 2 * jj];
        float x1 = qsrc[128 + 2 * jj + 1];
        qdst[128 + jj] = x0 * c - x1 * sn;
        qdst[160 + jj] = x1 * c + x0 * sn;
    } else if (tid < 192) {
        int jj = tid - 160;
        float ang = (float)s * g_invf[jj];
        float c = (float)cos((double)ang);
        float sn = (float)sin((double)ang);
        float x0 = krsrc[2 * jj];
        float x1 = krsrc[2 * jj + 1];
        kdst[128 + jj] = x0 * c - x1 * sn;
        kdst[160 + jj] = x1 * c + x0 * sn;
    }
}

// ---------------- V transpose ----------------
__global__ __launch_bounds__(256) void vtrans() {
    long idx = (long)blockIdx.x * 256 + threadIdx.x;
    const long total = (long)BHN * DV * SEQ;
    if (idx >= total) return;
    int s = (int)(idx % SEQ);
    long r = idx / SEQ;
    int d = (int)(r % DV);
    int bh = (int)(r / DV);
    int h = bh % NH, b = bh / NH;
    g_vt[idx] = g_kv[((size_t)b * SEQ + s) * (NH * 256) + (long)h * 256 + 128 + d];
}

// ---------------- causal softmax + fused bf16 hi/lo split ----------------
__global__ __launch_bounds__(256) void softmax_causal_split(
    float* __restrict__ attn,
    __nv_bfloat16* __restrict__ ah, __nv_bfloat16* __restrict__ al)
{
    const long r = blockIdx.x;               // bh*SEQ + q
    const int q = (int)(r % SEQ);
    float* row = attn + r * SEQ;
    __nv_bfloat16* hrow = ah + r * SEQ;
    __nv_bfloat16* lrow = al + r * SEQ;
    const int L = q + 1;
    __shared__ float red[8];

    float mx = -3.4e38f;
    for (int k = threadIdx.x; k < L; k += 256) mx = fmaxf(mx, row[k]);
#pragma unroll
    for (int o = 16; o; o >>= 1) mx = fmaxf(mx, __shfl_xor_sync(0xffffffffu, mx, o));
    if ((threadIdx.x & 31) == 0) red[threadIdx.x >> 5] = mx;
    __syncthreads();
    mx = fmaxf(fmaxf(fmaxf(red[0], red[1]), fmaxf(red[2], red[3])),
               fmaxf(fmaxf(red[4], red[5]), fmaxf(red[6], red[7])));
    __syncthreads();

    float s = 0.f;
    for (int k = threadIdx.x; k < L; k += 256) s += expf(row[k] - mx);
#pragma unroll
    for (int o = 16; o; o >>= 1) s += __shfl_xor_sync(0xffffffffu, s, o);
    if ((threadIdx.x & 31) == 0) red[threadIdx.x >> 5] = s;
    __syncthreads();
    s = red[0]+red[1]+red[2]+red[3]+red[4]+red[5]+red[6]+red[7];
    const float inv = 1.f / s;

    for (int k = threadIdx.x; k < L; k += 256) {
        float pv = expf(row[k] - mx) * inv;
        row[k] = pv;
        __nv_bfloat16 hi = __float2bfloat16(pv);
        hrow[k] = hi;
        lrow[k] = __float2bfloat16(pv - __bfloat162float(hi));
    }
    const __nv_bfloat16 zb = __float2bfloat16(0.f);
    for (int k = L + (int)threadIdx.x; k < SEQ; k += 256) {
        row[k] = 0.f; hrow[k] = zb; lrow[k] = zb;
    }
}

// ---------------- host launch ----------------
static inline int cdiv(long a, long b) { return (int)((a + b - 1) / b); }

extern "C" void kernel_launch(void* const* d_in, const int* in_sizes, int n_in,
                              void* d_out, int out_size)
{
    const float *hs = 0, *w_q_down = 0, *q_norm_w = 0, *w_q_up = 0;
    const float *w_kv_down = 0, *kv_norm_w = 0, *w_kv_up = 0, *w_out = 0;
    for (int i = 0; i < n_in; i++) {
        long n = in_sizes[i];
        const float* ptr = (const float*)d_in[i];
        if (n == 8388608)      { if (!hs) hs = ptr; }
        else if (n == 3145728) w_q_down = ptr;
        else if (n == 1536)    q_norm_w = ptr;
        else if (n == 4718592) w_q_up = ptr;
        else if (n == 1179648) w_kv_down = ptr;
        else if (n == 512)     kv_norm_w = ptr;
        else if (n == 2097152) w_kv_up = ptr;
        else if (n == 4194304) w_out = ptr;
    }

    float* out_final = (float*)d_out;

    void* p;
    cudaGetSymbolAddress(&p, g_q1);   float* q1   = (float*)p;
    cudaGetSymbolAddress(&p, g_q);    float* q    = (float*)p;
    cudaGetSymbolAddress(&p, g_c);    float* c    = (float*)p;
    cudaGetSymbolAddress(&p, g_ckvn); float* ckvn = (float*)p;
    cudaGetSymbolAddress(&p, g_kv);   float* kv   = (float*)p;
    cudaGetSymbolAddress(&p, g_qbuf); float* qb   = (float*)p;
    cudaGetSymbolAddress(&p, g_kbuf); float* kb   = (float*)p;
    cudaGetSymbolAddress(&p, g_vt);   float* vt   = (float*)p;
    cudaGetSymbolAddress(&p, g_om);   float* om   = (float*)p;
    cudaGetSymbolAddress(&p, g_attn); float* attn_scratch = (float*)p;

    __nv_bfloat16 *hsh, *hsl, *wqdh, *wqdl, *wquh, *wqul, *wkdh, *wkdl, *wkuh, *wkul, *woh, *wol;
    __nv_bfloat16 *q1h, *q1l, *ckh, *ckl, *omh, *oml;
    __nv_bfloat16 *qbh, *qbl, *kbh, *kbl, *vth, *vtl, *ath, *atl;
    cudaGetSymbolAddress(&p, b_hs_h);  hsh  = (__nv_bfloat16*)p;
    cudaGetSymbolAddress(&p, b_hs_l);  hsl  = (__nv_bfloat16*)p;
    cudaGetSymbolAddress(&p, b_wqd_h); wqdh = (__nv_bfloat16*)p;
    cudaGetSymbolAddress(&p, b_wqd_l); wqdl = (__nv_bfloat16*)p;
    cudaGetSymbolAddress(&p, b_wqu_h); wquh = (__nv_bfloat16*)p;
    cudaGetSymbolAddress(&p, b_wqu_l); wqul = (__nv_bfloat16*)p;
    cudaGetSymbolAddress(&p, b_wkd_h); wkdh = (__nv_bfloat16*)p;
    cudaGetSymbolAddress(&p, b_wkd_l); wkdl = (__nv_bfloat16*)p;
    cudaGetSymbolAddress(&p, b_wku_h); wkuh = (__nv_bfloat16*)p;
    cudaGetSymbolAddress(&p, b_wku_l); wkul = (__nv_bfloat16*)p;
    cudaGetSymbolAddress(&p, b_wo_h);  woh  = (__nv_bfloat16*)p;
    cudaGetSymbolAddress(&p, b_wo_l);  wol  = (__nv_bfloat16*)p;
    cudaGetSymbolAddress(&p, b_q1_h);  q1h  = (__nv_bfloat16*)p;
    cudaGetSymbolAddress(&p, b_q1_l);  q1l  = (__nv_bfloat16*)p;
    cudaGetSymbolAddress(&p, b_ck_h);  ckh  = (__nv_bfloat16*)p;
    cudaGetSymbolAddress(&p, b_ck_l);  ckl  = (__nv_bfloat16*)p;
    cudaGetSymbolAddress(&p, b_om_h);  omh  = (__nv_bfloat16*)p;
    cudaGetSymbolAddress(&p, b_om_l);  oml  = (__nv_bfloat16*)p;
    cudaGetSymbolAddress(&p, b_qb_h);  qbh  = (__nv_bfloat16*)p;
    cudaGetSymbolAddress(&p, b_qb_l);  qbl  = (__nv_bfloat16*)p;
    cudaGetSymbolAddress(&p, b_kb_h);  kbh  = (__nv_bfloat16*)p;
    cudaGetSymbolAddress(&p, b_kb_l);  kbl  = (__nv_bfloat16*)p;
    cudaGetSymbolAddress(&p, b_vt_h);  vth  = (__nv_bfloat16*)p;
    cudaGetSymbolAddress(&p, b_vt_l);  vtl  = (__nv_bfloat16*)p;
    cudaGetSymbolAddress(&p, b_at_h);  ath  = (__nv_bfloat16*)p;
    cudaGetSymbolAddress(&p, b_at_l);  atl  = (__nv_bfloat16*)p;

    const size_t need = (size_t)TOK * HID + (size_t)BHN * SEQ * SEQ;
    float* attn_out = ((size_t)out_size >= need)
                    ? (float*)d_out + (size_t)TOK * HID
                    : attn_scratch;

    const float qk_scale = 1.0f / sqrtf((float)DQK);

    init_rope<<<1, 32>>>();

    // split inputs + weights to bf16 hi/lo
    { long n = (long)TOK*HID;              split_bf16<<<cdiv(n,256),256>>>(hs, hsh, hsl, n); }
    { long n = (long)QLORA*HID;            split_bf16<<<cdiv(n,256),256>>>(w_q_down, wqdh, wqdl, n); }
    { long n = (long)(NH*DQK)*QLORA;       split_bf16<<<cdiv(n,256),256>>>(w_q_up, wquh, wqul, n); }
    { long n = (long)(KVLORA+ROPE_D)*HID;  split_bf16<<<cdiv(n,256),256>>>(w_kv_down, wkdh, wkdl, n); }
    { long n = (long)(NH*256)*KVLORA;      split_bf16<<<cdiv(n,256),256>>>(w_kv_up, wkuh, wkul, n); }
    { long n = (long)HID*(NH*DV);          split_bf16<<<cdiv(n,256),256>>>(w_out, woh, wol, n); }

    // q1 = hs @ w_q_down^T  [4096 x 1536], K=2048
    mma_gemm<<<dim3(QLORA/128, TOK/128), 256>>>(
        hsh, hsl, wqdh, wqdl, q1,
        HID, 0, HID, 0, QLORA, 0, 0, 1,
        TOK, QLORA, HID, 1.f, 0);
    rmsnorm_k<<<TOK, 256>>>(q1, QLORA, q_norm_w, q1, QLORA, QLORA);
    { long n = (long)TOK*QLORA; split_bf16<<<cdiv(n,256),256>>>(q1, q1h, q1l, n); }

    // q = q1n @ w_q_up^T  [4096 x 3072], K=1536
    mma_gemm<<<dim3((NH*DQK)/128, TOK/128), 256>>>(
        q1h, q1l, wquh, wqul, q,
        QLORA, 0, QLORA, 0, NH*DQK, 0, 0, 1,
        TOK, NH*DQK, QLORA, 1.f, 0);

    // c = hs @ w_kv_down^T  [4096 x 576], K=2048
    mma_gemm<<<dim3(cdiv(KVLORA+ROPE_D,128), TOK/128), 256>>>(
        hsh, hsl, wkdh, wkdl, c,
        HID, 0, HID, 0, KVLORA+ROPE_D, 0, 0, 1,
        TOK, KVLORA+ROPE_D, HID, 1.f, 0);
    rmsnorm_k<<<TOK, 256>>>(c, KVLORA+ROPE_D, kv_norm_w, ckvn, KVLORA, KVLORA);
    { long n = (long)TOK*KVLORA; split_bf16<<<cdiv(n,256),256>>>(ckvn, ckh, ckl, n); }

    // kv = ckvn @ w_kv_up^T  [4096 x 4096], K=512
    mma_gemm<<<dim3((NH*256)/128, TOK/128), 256>>>(
        ckh, ckl, wkuh, wkul, kv,
        KVLORA, 0, KVLORA, 0, NH*256, 0, 0, 1,
        TOK, NH*256, KVLORA, 1.f, 0);

    // RoPE pack of Q/K, V transpose
    rope_pack<<<BHN*SEQ, 256>>>();
    {
        long total = (long)BHN * DV * SEQ;
        vtrans<<<(int)((total + 255) / 256), 256>>>();
    }

    // split attention operands
    { long n = (long)BHN*SEQ*DQK; split_bf16<<<cdiv(n,256),256>>>(qb, qbh, qbl, n); }
    { long n = (long)BHN*SEQ*DQK; split_bf16<<<cdiv(n,256),256>>>(kb, kbh, kbl, n); }
    { long n = (long)BHN*DV*SEQ;  split_bf16<<<cdiv(n,256),256>>>(vt, vth, vtl, n); }

    // scores: attn[bh] = qk_scale * Q @ K^T  (causal tile skip) — tensor cores
    mma_gemm<<<dim3(SEQ/128, SEQ/128, BHN), 256>>>(
        qbh, qbl, kbh, kbl, attn_out,
        DQK, (long)SEQ*DQK, DQK, (long)SEQ*DQK,
        SEQ, (long)SEQ*SEQ, 0, 1,
        SEQ, SEQ, DQK, qk_scale, 1);

    // softmax + fused hi/lo split
    softmax_causal_split<<<BHN*SEQ, 256>>>(attn_out, ath, atl);

    // O = attn @ V (K clamped causally) — tensor cores
    mma_gemm<<<dim3(DV/128, SEQ/128, BHN), 256>>>(
        ath, atl, vth, vtl, om,
        SEQ, (long)SEQ*SEQ, SEQ, (long)DV*SEQ,
        NH*DV, (long)SEQ*NH*DV, DV, NH,
        SEQ, DV, SEQ, 1.f, 2);

    // out = om @ w_out^T  [4096 x 2048], K=2048
    { long n = (long)TOK*(NH*DV); split_bf16<<<cdiv(n,256),256>>>(om, omh, oml, n); }
    mma_gemm<<<dim3(HID/128, TOK/128), 256>>>(
        omh, oml, woh, wol, out_final,
        NH*DV, 0, NH*DV, 0, HID, 0, 0, 1,
        TOK, HID, NH*DV, 1.f, 0);
}

// round 12
// speedup vs baseline: 3.8287x; 1.0799x over previous
#include <cuda_runtime.h>
#include <cuda_bf16.h>
#include <math.h>
#include <stdint.h>

// ---------------- problem constants ----------------
#define BATCH 2
#define SEQ   2048
#define HID   2048
#define NH    16
#define DQK   192
#define DV    128
#define QLORA 1536
#define KVLORA 512
#define ROPE_D 64
#define TOK   (BATCH*SEQ)          // 4096
#define BHN   (BATCH*NH)           // 32

// ---------------- fp32 scratch ----------------
__device__ float g_q1 [(size_t)TOK * QLORA];      // pre-norm q1 (fp32 needed for rmsnorm input)
__device__ float g_q  [(size_t)TOK * (NH*DQK)];
__device__ float g_c  [(size_t)TOK * (KVLORA+ROPE_D)];
__device__ float g_kv [(size_t)TOK * (NH*256)];
__device__ float g_om [(size_t)TOK * (NH*DV)];
__device__ float g_attn[(size_t)BHN * SEQ * SEQ];
__device__ float g_invf[32];

// ---------------- bf16 split buffers (hi/lo) ----------------
__device__ __nv_bfloat16 b_hs_h [(size_t)TOK*HID],      b_hs_l [(size_t)TOK*HID];
__device__ __nv_bfloat16 b_wqd_h[(size_t)QLORA*HID],    b_wqd_l[(size_t)QLORA*HID];
__device__ __nv_bfloat16 b_wqu_h[(size_t)(NH*DQK)*QLORA], b_wqu_l[(size_t)(NH*DQK)*QLORA];
__device__ __nv_bfloat16 b_wkd_h[(size_t)(KVLORA+ROPE_D)*HID], b_wkd_l[(size_t)(KVLORA+ROPE_D)*HID];
__device__ __nv_bfloat16 b_wku_h[(size_t)(NH*256)*KVLORA], b_wku_l[(size_t)(NH*256)*KVLORA];
__device__ __nv_bfloat16 b_wo_h [(size_t)HID*(NH*DV)],  b_wo_l [(size_t)HID*(NH*DV)];
__device__ __nv_bfloat16 b_q1_h [(size_t)TOK*QLORA],    b_q1_l [(size_t)TOK*QLORA];
__device__ __nv_bfloat16 b_ck_h [(size_t)TOK*KVLORA],   b_ck_l [(size_t)TOK*KVLORA];
__device__ __nv_bfloat16 b_om_h [(size_t)TOK*(NH*DV)],  b_om_l [(size_t)TOK*(NH*DV)];
__device__ __nv_bfloat16 b_qb_h [(size_t)BHN*SEQ*DQK],  b_qb_l [(size_t)BHN*SEQ*DQK];
__device__ __nv_bfloat16 b_kb_h [(size_t)BHN*SEQ*DQK],  b_kb_l [(size_t)BHN*SEQ*DQK];
__device__ __nv_bfloat16 b_vt_h [(size_t)BHN*DV*SEQ],   b_vt_l [(size_t)BHN*DV*SEQ];
__device__ __nv_bfloat16 b_at_h [(size_t)BHN*SEQ*SEQ],  b_at_l [(size_t)BHN*SEQ*SEQ];

// ================= helpers =================
__device__ __forceinline__ uint32_t smem_u32(const void* p) {
    uint32_t a;
    asm("{ .reg .u64 t; cvta.to.shared.u64 t, %1; cvt.u32.u64 %0, t; }" : "=r"(a) : "l"(p));
    return a;
}
__device__ __forceinline__ void ldmx4(uint32_t* r, uint32_t addr) {
    asm volatile("ldmatrix.sync.aligned.m8n8.x4.shared.b16 {%0,%1,%2,%3}, [%4];"
        : "=r"(r[0]), "=r"(r[1]), "=r"(r[2]), "=r"(r[3]) : "r"(addr));
}
__device__ __forceinline__ void mma_bf16(float* d, const uint32_t* a, const uint32_t* b) {
    asm volatile("mma.sync.aligned.m16n8k16.row.col.f32.bf16.bf16.f32 "
        "{%0,%1,%2,%3}, {%4,%5,%6,%7}, {%8,%9}, {%0,%1,%2,%3};"
        : "+f"(d[0]), "+f"(d[1]), "+f"(d[2]), "+f"(d[3])
        : "r"(a[0]), "r"(a[1]), "r"(a[2]), "r"(a[3]), "r"(b[0]), "r"(b[1]));
}
__device__ __forceinline__ void cp16(uint32_t dst, const void* src, bool v) {
    int sz = v ? 16 : 0;
    asm volatile("cp.async.cg.shared.global [%0], [%1], 16, %2;"
        :: "r"(dst), "l"(src), "r"(sz) : "memory");
}
#define CP_COMMIT() asm volatile("cp.async.commit_group;" ::: "memory")
#define CP_WAIT(n)  asm volatile("cp.async.wait_group %0;" :: "n"(n) : "memory")

// ---------------- batched split-bf16 tensor GEMM, cp.async 2-stage -------
// C = alpha * (Ah+Al) * (Bh+Bl)^T  (3-pass compensation, fp32 accum)
// mode 0 plain; 1 causal tile-skip; 2 K clamped to m0+128.
#define TSTR 40                    // smem row stride in bf16
#define BUFB (128*TSTR*2)          // 10240 bytes per tile buffer
#define STG  (4*BUFB)              // 40960 bytes per stage
#define SMEM_TOTAL (2*STG)         // 81920

__global__ __launch_bounds__(256, 2) void mma_gemm(
    const __nv_bfloat16* __restrict__ Ah, const __nv_bfloat16* __restrict__ Al,
    const __nv_bfloat16* __restrict__ Bh, const __nv_bfloat16* __restrict__ Bl,
    float* __restrict__ C,
    long lda, long sA, long ldb, long sB,
    long ldc, long sC, long sC2, int zdiv,
    int M, int N, int K, float alpha, int mode)
{
    extern __shared__ char dsm[];
    const uint32_t sb = smem_u32(dsm);

    const int z = blockIdx.z;
    const __nv_bfloat16* Abh = Ah + (size_t)z * sA;
    const __nv_bfloat16* Abl = Al + (size_t)z * sA;
    const __nv_bfloat16* Bbh = Bh + (size_t)z * sB;
    const __nv_bfloat16* Bbl = Bl + (size_t)z * sB;
    float* Cb = C + (size_t)(z / zdiv) * sC + (size_t)(z % zdiv) * sC2;

    const int tid = threadIdx.x;
    const int lane = tid & 31;
    const int wid = tid >> 5;
    const int wm = wid >> 2;
    const int wn = wid & 3;
    const int m0 = blockIdx.y * 128, n0 = blockIdx.x * 128;
    if (mode == 1 && n0 >= m0 + 128) return;
    int Keff = (mode == 2) ? min(K, m0 + 128) : K;
    const int nk = Keff / 32;

    float acc[4][4][4];
#pragma unroll
    for (int i = 0; i < 4; i++)
#pragma unroll
        for (int j = 0; j < 4; j++)
#pragma unroll
            for (int f = 0; f < 4; f++) acc[i][j][f] = 0.f;

    const int a_row = wm * 64 + (lane & 15);
    const int a_col = ((lane >> 4) & 1) * 8;
    const int b_row = wn * 32 + ((lane >> 4) & 1) * 8 + (lane & 7);
    const int b_col = ((lane >> 3) & 1) * 8;

    // per-thread load slots: rows r0c, r0c+64; 16B column chunk c0
    const int r0c = tid >> 2, c0 = (tid & 3) * 8;
    const int r1c = r0c + 64;
    const uint32_t o0 = (uint32_t)(r0c * TSTR + c0) * 2;
    const uint32_t o1 = (uint32_t)(r1c * TSTR + c0) * 2;
    const bool v0 = (n0 + r0c) < N, v1 = (n0 + r1c) < N;
    const int bn0 = v0 ? (n0 + r0c) : 0, bn1 = v1 ? (n0 + r1c) : 0;

    auto issue = [&](int s, int k0) {
        const uint32_t base = sb + s * STG;
        const size_t a0o = (size_t)(m0 + r0c) * lda + k0 + c0;
        const size_t a1o = (size_t)(m0 + r1c) * lda + k0 + c0;
        cp16(base + o0, Abh + a0o, true);
        cp16(base + BUFB + o0, Abl + a0o, true);
        cp16(base + o1, Abh + a1o, true);
        cp16(base + BUFB + o1, Abl + a1o, true);
        const size_t b0o = (size_t)bn0 * ldb + k0 + c0;
        const size_t b1o = (size_t)bn1 * ldb + k0 + c0;
        cp16(base + 2*BUFB + o0, Bbh + b0o, v0);
        cp16(base + 3*BUFB + o0, Bbl + b0o, v0);
        cp16(base + 2*BUFB + o1, Bbh + b1o, v1);
        cp16(base + 3*BUFB + o1, Bbl + b1o, v1);
    };

    issue(0, 0);
    CP_COMMIT();

    for (int it = 0; it < nk; it++) {
        if (it + 1 < nk) {
            issue((it + 1) & 1, (it + 1) * 32);
            CP_COMMIT();
            CP_WAIT(1);
        } else {
            CP_WAIT(0);
        }
        __syncthreads();

        const uint32_t base = sb + (it & 1) * STG;
        const uint32_t aH = base, aL = base + BUFB;
        const uint32_t bH = base + 2*BUFB, bL = base + 3*BUFB;

#pragma unroll
        for (int k16 = 0; k16 < 2; k16++) {
            const int kc = k16 * 16;
            uint32_t bh[4][2], bl[4][2], af[4][4];
#pragma unroll
            for (int g = 0; g < 2; g++) {
                uint32_t r[4];
                uint32_t off = ((b_row + g * 16) * TSTR + kc + b_col) * 2;
                ldmx4(r, bH + off);
                bh[2*g][0] = r[0]; bh[2*g][1] = r[1];
                bh[2*g+1][0] = r[2]; bh[2*g+1][1] = r[3];
                ldmx4(r, bL + off);
                bl[2*g][0] = r[0]; bl[2*g][1] = r[1];
                bl[2*g+1][0] = r[2]; bl[2*g+1][1] = r[3];
            }
#pragma unroll
            for (int mi = 0; mi < 4; mi++)
                ldmx4(af[mi], aH + ((a_row + mi * 16) * TSTR + kc + a_col) * 2);
#pragma unroll
            for (int mi = 0; mi < 4; mi++)
#pragma unroll
                for (int nj = 0; nj < 4; nj++) {
                    mma_bf16(acc[mi][nj], af[mi], bh[nj]);
                    mma_bf16(acc[mi][nj], af[mi], bl[nj]);
                }
#pragma unroll
            for (int mi = 0; mi < 4; mi++)
                ldmx4(af[mi], aL + ((a_row + mi * 16) * TSTR + kc + a_col) * 2);
#pragma unroll
            for (int mi = 0; mi < 4; mi++)
#pragma unroll
                for (int nj = 0; nj < 4; nj++)
                    mma_bf16(acc[mi][nj], af[mi], bh[nj]);
        }
        __syncthreads();
    }

#pragma unroll
    for (int mi = 0; mi < 4; mi++) {
        const int m1 = m0 + wm * 64 + mi * 16 + (lane >> 2);
        const int m2 = m1 + 8;
#pragma unroll
        for (int nj = 0; nj < 4; nj++) {
            const int n = n0 + wn * 32 + nj * 8 + (lane & 3) * 2;
            if (n < N) {
                *(float2*)&Cb[(size_t)m1 * ldc + n] =
                    make_float2(alpha * acc[mi][nj][0], alpha * acc[mi][nj][1]);
                *(float2*)&Cb[(size_t)m2 * ldc + n] =
                    make_float2(alpha * acc[mi][nj][2], alpha * acc[mi][nj][3]);
            }
        }
    }
}

// ---------------- fp32 -> (hi, lo) bf16 splitter ----------------
__global__ __launch_bounds__(256) void split_bf16(
    const float* __restrict__ x, __nv_bfloat16* __restrict__ h,
    __nv_bfloat16* __restrict__ l, long n)
{
    long i = (long)blockIdx.x * 256 + threadIdx.x;
    if (i >= n) return;
    float v = x[i];
    __nv_bfloat16 hi = __float2bfloat16(v);
    h[i] = hi;
    l[i] = __float2bfloat16(v - __bfloat162float(hi));
}

// ---------------- RMSNorm with fused bf16 hi/lo output ----------------
__global__ __launch_bounds__(256) void rmsnorm_split(
    const float* __restrict__ in, long ldin,
    const float* __restrict__ w,
    __nv_bfloat16* __restrict__ oh, __nv_bfloat16* __restrict__ ol,
    long ldout, int D)
{
    const int row = blockIdx.x;
    const float* x = in + (size_t)row * ldin;
    __nv_bfloat16* h = oh + (size_t)row * ldout;
    __nv_bfloat16* l = ol + (size_t)row * ldout;

    float s = 0.f;
    for (int i = threadIdx.x; i < D; i += 256) { float v = x[i]; s += v * v; }
    __shared__ float red[8];
#pragma unroll
    for (int off = 16; off; off >>= 1) s += __shfl_xor_sync(0xffffffffu, s, off);
    if ((threadIdx.x & 31) == 0) red[threadIdx.x >> 5] = s;
    __syncthreads();
    float tot = red[0]+red[1]+red[2]+red[3]+red[4]+red[5]+red[6]+red[7];
    const float inv = rsqrtf(tot / (float)D + 1e-6f);
    for (int i = threadIdx.x; i < D; i += 256) {
        float v = w[i] * x[i] * inv;
        __nv_bfloat16 hi = __float2bfloat16(v);
        h[i] = hi;
        l[i] = __float2bfloat16(v - __bfloat162float(hi));
    }
}

// ---------------- RoPE table ----------------
__global__ void init_rope() {
    int j = threadIdx.x;
    if (j < 32)
        g_invf[j] = (float)exp(-((double)(2 * j) / 64.0) * log(10000.0));
}

// ---------------- fused RoPE pack -> bf16 hi/lo directly ----------------
__global__ __launch_bounds__(256) void rope_pack(
    __nv_bfloat16* __restrict__ qh, __nv_bfloat16* __restrict__ ql,
    __nv_bfloat16* __restrict__ kh, __nv_bfloat16* __restrict__ kl)
{
    const int blk = blockIdx.x;          // bh*SEQ + s
    const int s  = blk % SEQ;
    const int bh = blk / SEQ;
    const int h = bh % NH, b = bh / NH;
    const long t = (long)b * SEQ + s;
    const int tid = threadIdx.x;

    const size_t dst = (size_t)blk * DQK;
    const float* qsrc  = g_q  + t * (NH * DQK) + (long)h * DQK;
    const float* knsrc = g_kv + t * (NH * 256) + (long)h * 256;
    const float* krsrc = g_c  + t * (KVLORA + ROPE_D) + KVLORA;

    float qv0 = 0.f, qv1 = 0.f, kv0 = 0.f, kv1 = 0.f;
    int i0 = -1, i1 = -1;
    bool doq = false, dok = false;

    if (tid < 128) {
        qv0 = qsrc[tid]; kv0 = knsrc[tid];
        i0 = tid; doq = true; dok = true;
        // write single position for both q and k
        __nv_bfloat16 hq = __float2bfloat16(qv0);
        qh[dst + i0] = hq; ql[dst + i0] = __float2bfloat16(qv0 - __bfloat162float(hq));
        __nv_bfloat16 hk = __float2bfloat16(kv0);
        kh[dst + i0] = hk; kl[dst + i0] = __float2bfloat16(kv0 - __bfloat162float(hk));
        return;
    } else if (tid < 160) {
        int jj = tid - 128;
        float ang = (float)s * g_invf[jj];
        float c = (float)cos((double)ang);
        float sn = (float)sin((double)ang);
        float x0 = qsrc[128 + 2 * jj];
        float x1 = qsrc[128 + 2 * jj + 1];
        qv0 = x0 * c - x1 * sn;    i0 = 128 + jj;
        qv1 = x1 * c + x0 * sn;    i1 = 160 + jj;
        __nv_bfloat16 h0 = __float2bfloat16(qv0);
        qh[dst + i0] = h0; ql[dst + i0] = __float2bfloat16(qv0 - __bfloat162float(h0));
        __nv_bfloat16 h1 = __float2bfloat16(qv1);
        qh[dst + i1] = h1; ql[dst + i1] = __float2bfloat16(qv1 - __bfloat162float(h1));
        return;
    } else if (tid < 192) {
        int jj = tid - 160;
        float ang = (float)s * g_invf[jj];
        float c = (float)cos((double)ang);
        float sn = (float)sin((double)ang);
        float x0 = krsrc[2 * jj];
        float x1 = krsrc[2 * jj + 1];
        kv0 = x0 * c - x1 * sn;    i0 = 128 + jj;
        kv1 = x1 * c + x0 * sn;    i1 = 160 + jj;
        __nv_bfloat16 h0 = __float2bfloat16(kv0);
        kh[dst + i0] = h0; kl[dst + i0] = __float2bfloat16(kv0 - __bfloat162float(h0));
        __nv_bfloat16 h1 = __float2bfloat16(kv1);
        kh[dst + i1] = h1; kl[dst + i1] = __float2bfloat16(kv1 - __bfloat162float(h1));
        return;
    }
    (void)doq; (void)dok; (void)qv1; (void)kv1; (void)i1;
}

// ---------------- V transpose -> bf16 hi/lo directly ----------------
__global__ __launch_bounds__(256) void vtrans(
    __nv_bfloat16* __restrict__ vh, __nv_bfloat16* __restrict__ vl)
{
    long idx = (long)blockIdx.x * 256 + threadIdx.x;
    const long total = (long)BHN * DV * SEQ;
    if (idx >= total) return;
    int s = (int)(idx % SEQ);
    long r = idx / SEQ;
    int d = (int)(r % DV);
    int bh = (int)(r / DV);
    int h = bh % NH, b = bh / NH;
    float v = g_kv[((size_t)b * SEQ + s) * (NH * 256) + (long)h * 256 + 128 + d];
    __nv_bfloat16 hi = __float2bfloat16(v);
    vh[idx] = hi;
    vl[idx] = __float2bfloat16(v - __bfloat162float(hi));
}

// ---------------- causal softmax + fused bf16 hi/lo split ----------------
// fp32 zeros written to SEQ (required in output); bf16 zeros only to the
// 128-aligned boundary actually read by the K-clamped PV GEMM.
__global__ __launch_bounds__(256) void softmax_causal_split(
    float* __restrict__ attn,
    __nv_bfloat16* __restrict__ ah, __nv_bfloat16* __restrict__ al)
{
    const long r = blockIdx.x;               // bh*SEQ + q
    const int q = (int)(r % SEQ);
    float* row = attn + r * SEQ;
    __nv_bfloat16* hrow = ah + r * SEQ;
    __nv_bfloat16* lrow = al + r * SEQ;
    const int L = q + 1;
    const int Lc = (L + 127) & ~127;         // PV reads keys [0, Lc)
    __shared__ float red[8];

    float mx = -3.4e38f;
    for (int k = threadIdx.x; k < L; k += 256) mx = fmaxf(mx, row[k]);
#pragma unroll
    for (int o = 16; o; o >>= 1) mx = fmaxf(mx, __shfl_xor_sync(0xffffffffu, mx, o));
    if ((threadIdx.x & 31) == 0) red[threadIdx.x >> 5] = mx;
    __syncthreads();
    mx = fmaxf(fmaxf(fmaxf(red[0], red[1]), fmaxf(red[2], red[3])),
               fmaxf(fmaxf(red[4], red[5]), fmaxf(red[6], red[7])));
    __syncthreads();

    float s = 0.f;
    for (int k = threadIdx.x; k < L; k += 256) s += expf(row[k] - mx);
#pragma unroll
    for (int o = 16; o; o >>= 1) s += __shfl_xor_sync(0xffffffffu, s, o);
    if ((threadIdx.x & 31) == 0) red[threadIdx.x >> 5] = s;
    __syncthreads();
    s = red[0]+red[1]+red[2]+red[3]+red[4]+red[5]+red[6]+red[7];
    const float inv = 1.f / s;

    for (int k = threadIdx.x; k < L; k += 256) {
        float pv = expf(row[k] - mx) * inv;
        row[k] = pv;
        __nv_bfloat16 hi = __float2bfloat16(pv);
        hrow[k] = hi;
        lrow[k] = __float2bfloat16(pv - __bfloat162float(hi));
    }
    const __nv_bfloat16 zb = __float2bfloat16(0.f);
    for (int k = L + (int)threadIdx.x; k < Lc; k += 256) { hrow[k] = zb; lrow[k] = zb; }
    for (int k = L + (int)threadIdx.x; k < SEQ; k += 256) row[k] = 0.f;
}

// ---------------- host launch ----------------
static inline int cdiv(long a, long b) { return (int)((a + b - 1) / b); }

extern "C" void kernel_launch(void* const* d_in, const int* in_sizes, int n_in,
                              void* d_out, int out_size)
{
    const float *hs = 0, *w_q_down = 0, *q_norm_w = 0, *w_q_up = 0;
    const float *w_kv_down = 0, *kv_norm_w = 0, *w_kv_up = 0, *w_out = 0;
    for (int i = 0; i < n_in; i++) {
        long n = in_sizes[i];
        const float* ptr = (const float*)d_in[i];
        if (n == 8388608)      { if (!hs) hs = ptr; }
        else if (n == 3145728) w_q_down = ptr;
        else if (n == 1536)    q_norm_w = ptr;
        else if (n == 4718592) w_q_up = ptr;
        else if (n == 1179648) w_kv_down = ptr;
        else if (n == 512)     kv_norm_w = ptr;
        else if (n == 2097152) w_kv_up = ptr;
        else if (n == 4194304) w_out = ptr;
    }

    float* out_final = (float*)d_out;

    void* p;
    cudaGetSymbolAddress(&p, g_q1);   float* q1   = (float*)p;
    cudaGetSymbolAddress(&p, g_q);    float* q    = (float*)p;
    cudaGetSymbolAddress(&p, g_c);    float* c    = (float*)p;
    cudaGetSymbolAddress(&p, g_kv);   float* kv   = (float*)p;
    cudaGetSymbolAddress(&p, g_om);   float* om   = (float*)p;
    cudaGetSymbolAddress(&p, g_attn); float* attn_scratch = (float*)p;

    __nv_bfloat16 *hsh, *hsl, *wqdh, *wqdl, *wquh, *wqul, *wkdh, *wkdl, *wkuh, *wkul, *woh, *wol;
    __nv_bfloat16 *q1h, *q1l, *ckh, *ckl, *omh, *oml;
    __nv_bfloat16 *qbh, *qbl, *kbh, *kbl, *vth, *vtl, *ath, *atl;
    cudaGetSymbolAddress(&p, b_hs_h);  hsh  = (__nv_bfloat16*)p;
    cudaGetSymbolAddress(&p, b_hs_l);  hsl  = (__nv_bfloat16*)p;
    cudaGetSymbolAddress(&p, b_wqd_h); wqdh = (__nv_bfloat16*)p;
    cudaGetSymbolAddress(&p, b_wqd_l); wqdl = (__nv_bfloat16*)p;
    cudaGetSymbolAddress(&p, b_wqu_h); wquh = (__nv_bfloat16*)p;
    cudaGetSymbolAddress(&p, b_wqu_l); wqul = (__nv_bfloat16*)p;
    cudaGetSymbolAddress(&p, b_wkd_h); wkdh = (__nv_bfloat16*)p;
    cudaGetSymbolAddress(&p, b_wkd_l); wkdl = (__nv_bfloat16*)p;
    cudaGetSymbolAddress(&p, b_wku_h); wkuh = (__nv_bfloat16*)p;
    cudaGetSymbolAddress(&p, b_wku_l); wkul = (__nv_bfloat16*)p;
    cudaGetSymbolAddress(&p, b_wo_h);  woh  = (__nv_bfloat16*)p;
    cudaGetSymbolAddress(&p, b_wo_l);  wol  = (__nv_bfloat16*)p;
    cudaGetSymbolAddress(&p, b_q1_h);  q1h  = (__nv_bfloat16*)p;
    cudaGetSymbolAddress(&p, b_q1_l);  q1l  = (__nv_bfloat16*)p;
    cudaGetSymbolAddress(&p, b_ck_h);  ckh  = (__nv_bfloat16*)p;
    cudaGetSymbolAddress(&p, b_ck_l);  ckl  = (__nv_bfloat16*)p;
    cudaGetSymbolAddress(&p, b_om_h);  omh  = (__nv_bfloat16*)p;
    cudaGetSymbolAddress(&p, b_om_l);  oml  = (__nv_bfloat16*)p;
    cudaGetSymbolAddress(&p, b_qb_h);  qbh  = (__nv_bfloat16*)p;
    cudaGetSymbolAddress(&p, b_qb_l);  qbl  = (__nv_bfloat16*)p;
    cudaGetSymbolAddress(&p, b_kb_h);  kbh  = (__nv_bfloat16*)p;
    cudaGetSymbolAddress(&p, b_kb_l);  kbl  = (__nv_bfloat16*)p;
    cudaGetSymbolAddress(&p, b_vt_h);  vth  = (__nv_bfloat16*)p;
    cudaGetSymbolAddress(&p, b_vt_l);  vtl  = (__nv_bfloat16*)p;
    cudaGetSymbolAddress(&p, b_at_h);  ath  = (__nv_bfloat16*)p;
    cudaGetSymbolAddress(&p, b_at_l);  atl  = (__nv_bfloat16*)p;

    cudaFuncSetAttribute(mma_gemm, cudaFuncAttributeMaxDynamicSharedMemorySize, SMEM_TOTAL);

    const size_t need = (size_t)TOK * HID + (size_t)BHN * SEQ * SEQ;
    float* attn_out = ((size_t)out_size >= need)
                    ? (float*)d_out + (size_t)TOK * HID
                    : attn_scratch;

    const float qk_scale = 1.0f / sqrtf((float)DQK);

    init_rope<<<1, 32>>>();

    // split inputs + weights to bf16 hi/lo
    { long n = (long)TOK*HID;              split_bf16<<<cdiv(n,256),256>>>(hs, hsh, hsl, n); }
    { long n = (long)QLORA*HID;            split_bf16<<<cdiv(n,256),256>>>(w_q_down, wqdh, wqdl, n); }
    { long n = (long)(NH*DQK)*QLORA;       split_bf16<<<cdiv(n,256),256>>>(w_q_up, wquh, wqul, n); }
    { long n = (long)(KVLORA+ROPE_D)*HID;  split_bf16<<<cdiv(n,256),256>>>(w_kv_down, wkdh, wkdl, n); }
    { long n = (long)(NH*256)*KVLORA;      split_bf16<<<cdiv(n,256),256>>>(w_kv_up, wkuh, wkul, n); }
    { long n = (long)HID*(NH*DV);          split_bf16<<<cdiv(n,256),256>>>(w_out, woh, wol, n); }

    // q1 = hs @ w_q_down^T  [4096 x 1536], K=2048
    mma_gemm<<<dim3(QLORA/128, TOK/128), 256, SMEM_TOTAL>>>(
        hsh, hsl, wqdh, wqdl, q1,
        HID, 0, HID, 0, QLORA, 0, 0, 1,
        TOK, QLORA, HID, 1.f, 0);
    rmsnorm_split<<<TOK, 256>>>(q1, QLORA, q_norm_w, q1h, q1l, QLORA, QLORA);

    // q = q1n @ w_q_up^T  [4096 x 3072], K=1536
    mma_gemm<<<dim3((NH*DQK)/128, TOK/128), 256, SMEM_TOTAL>>>(
        q1h, q1l, wquh, wqul, q,
        QLORA, 0, QLORA, 0, NH*DQK, 0, 0, 1,
        TOK, NH*DQK, QLORA, 1.f, 0);

    // c = hs @ w_kv_down^T  [4096 x 576], K=2048
    mma_gemm<<<dim3(cdiv(KVLORA+ROPE_D,128), TOK/128), 256, SMEM_TOTAL>>>(
        hsh, hsl, wkdh, wkdl, c,
        HID, 0, HID, 0, KVLORA+ROPE_D, 0, 0, 1,
        TOK, KVLORA+ROPE_D, HID, 1.f, 0);
    rmsnorm_split<<<TOK, 256>>>(c, KVLORA+ROPE_D, kv_norm_w, ckh, ckl, KVLORA, KVLORA);

    // kv = ckvn @ w_kv_up^T  [4096 x 4096], K=512
    mma_gemm<<<dim3((NH*256)/128, TOK/128), 256, SMEM_TOTAL>>>(
        ckh, ckl, wkuh, wkul, kv,
        KVLORA, 0, KVLORA, 0, NH*256, 0, 0, 1,
        TOK, NH*256, KVLORA, 1.f, 0);

    // RoPE pack of Q/K (direct bf16 hi/lo), V transpose (direct bf16 hi/lo)
    rope_pack<<<BHN*SEQ, 256>>>(qbh, qbl, kbh, kbl);
    {
        long total = (long)BHN * DV * SEQ;
        vtrans<<<(int)((total + 255) / 256), 256>>>(vth, vtl);
    }

    // scores: attn[bh] = qk_scale * Q @ K^T  (causal tile skip)
    mma_gemm<<<dim3(SEQ/128, SEQ/128, BHN), 256, SMEM_TOTAL>>>(
        qbh, qbl, kbh, kbl, attn_out,
        DQK, (long)SEQ*DQK, DQK, (long)SEQ*DQK,
        SEQ, (long)SEQ*SEQ, 0, 1,
        SEQ, SEQ, DQK, qk_scale, 1);

    // softmax + fused hi/lo split
    softmax_causal_split<<<BHN*SEQ, 256>>>(attn_out, ath, atl);

    // O = attn @ V (K clamped causally)
    mma_gemm<<<dim3(DV/128, SEQ/128, BHN), 256, SMEM_TOTAL>>>(
        ath, atl, vth, vtl, om,
        SEQ, (long)SEQ*SEQ, SEQ, (long)DV*SEQ,
        NH*DV, (long)SEQ*NH*DV, DV, NH,
        SEQ, DV, SEQ, 1.f, 2);

    // out = om @ w_out^T  [4096 x 2048], K=2048
    { long n = (long)TOK*(NH*DV); split_bf16<<<cdiv(n,256),256>>>(om, omh, oml, n); }
    mma_gemm<<<dim3(HID/128, TOK/128), 256, SMEM_TOTAL>>>(
        omh, oml, woh, wol, out_final,
        NH*DV, 0, NH*DV, 0, HID, 0, 0, 1,
        TOK, HID, NH*DV, 1.f, 0);
}

// round 13
// speedup vs baseline: 4.5768x; 1.1954x over previous
#include <cuda_runtime.h>
#include <cuda_bf16.h>
#include <math.h>
#include <stdint.h>

// ---------------- problem constants ----------------
#define BATCH 2
#define SEQ   2048
#define HID   2048
#define NH    16
#define DQK   192
#define DV    128
#define QLORA 1536
#define KVLORA 512
#define ROPE_D 64
#define TOK   (BATCH*SEQ)          // 4096
#define BHN   (BATCH*NH)           // 32

// ---------------- fp32 scratch (all GEMM operands tf32-rounded fp32) -----
__device__ float g_q1  [(size_t)TOK * QLORA];
__device__ float g_q1n [(size_t)TOK * QLORA];
__device__ float g_q   [(size_t)TOK * (NH*DQK)];
__device__ float g_c   [(size_t)TOK * (KVLORA+ROPE_D)];
__device__ float g_ckn [(size_t)TOK * KVLORA];
__device__ float g_kv  [(size_t)TOK * (NH*256)];
__device__ float g_qbuf[(size_t)BHN * SEQ * DQK];
__device__ float g_kbuf[(size_t)BHN * SEQ * DQK];
__device__ float g_vt  [(size_t)BHN * DV * SEQ];
__device__ float g_om  [(size_t)TOK * (NH*DV)];
__device__ float g_attn[(size_t)BHN * SEQ * SEQ];
__device__ float g_invf[32];
// rounded copies of read-only inputs
__device__ float g_hsr [(size_t)TOK*HID];
__device__ float g_wqd [(size_t)QLORA*HID];
__device__ float g_wqu [(size_t)(NH*DQK)*QLORA];
__device__ float g_wkd [(size_t)(KVLORA+ROPE_D)*HID];
__device__ float g_wku [(size_t)(NH*256)*KVLORA];
__device__ float g_wo  [(size_t)HID*(NH*DV)];

// ================= helpers =================
__device__ __forceinline__ uint32_t smem_u32(const void* p) {
    uint32_t a;
    asm("{ .reg .u64 t; cvta.to.shared.u64 t, %1; cvt.u32.u64 %0, t; }" : "=r"(a) : "l"(p));
    return a;
}
__device__ __forceinline__ float rna_tf32(float x) {
    uint32_t t; asm("cvt.rna.tf32.f32 %0, %1;" : "=r"(t) : "f"(x));
    return __uint_as_float(t);
}
__device__ __forceinline__ void mma_tf32(float* d, const uint32_t* a, const uint32_t* b) {
    asm volatile("mma.sync.aligned.m16n8k8.row.col.f32.tf32.tf32.f32 "
        "{%0,%1,%2,%3}, {%4,%5,%6,%7}, {%8,%9}, {%0,%1,%2,%3};"
        : "+f"(d[0]), "+f"(d[1]), "+f"(d[2]), "+f"(d[3])
        : "r"(a[0]), "r"(a[1]), "r"(a[2]), "r"(a[3]), "r"(b[0]), "r"(b[1]));
}
__device__ __forceinline__ void cp16(uint32_t dst, const void* src, bool v) {
    int sz = v ? 16 : 0;
    asm volatile("cp.async.cg.shared.global [%0], [%1], 16, %2;"
        :: "r"(dst), "l"(src), "r"(sz) : "memory");
}
#define CP_COMMIT() asm volatile("cp.async.commit_group;" ::: "memory")
#define CP_WAIT(n)  asm volatile("cp.async.wait_group %0;" :: "n"(n) : "memory")

// ---------------- batched single-pass TF32 tensor GEMM, cp.async 2-stage --
// C = alpha * A * B^T   (A,B fp32 pre-rounded to tf32; fp32 accumulate)
// A: [M,K], row stride lda, batch stride sA.  B: [N,K], ldb, sB.
// C: fp32; batch base = C + (z/zdiv)*sC + (z%zdiv)*sC2.
// mode 0 plain; 1 causal tile-skip; 2 K clamped to m0+128. M%128==0, K%32==0.
#define TSTRF 36                   // smem row stride in floats
#define BUFF (128*TSTRF*4)         // 18432 B per tile buffer
#define STGF (2*BUFF)              // 36864 B per stage
#define SMEMF (2*STGF)             // 73728 B

__global__ __launch_bounds__(256, 2) void mma_gemm(
    const float* __restrict__ A, const float* __restrict__ B,
    float* __restrict__ C,
    long lda, long sA, long ldb, long sB,
    long ldc, long sC, long sC2, int zdiv,
    int M, int N, int K, float alpha, int mode)
{
    extern __shared__ char dsm[];
    const uint32_t sb = smem_u32(dsm);

    const int z = blockIdx.z;
    const float* Ab = A + (size_t)z * sA;
    const float* Bb = B + (size_t)z * sB;
    float* Cb = C + (size_t)(z / zdiv) * sC + (size_t)(z % zdiv) * sC2;

    const int tid = threadIdx.x;
    const int lane = tid & 31;
    const int wid = tid >> 5;
    const int wm = wid >> 2;          // 0..1 -> 64 rows
    const int wn = wid & 3;           // 0..3 -> 32 cols
    const int m0 = blockIdx.y * 128, n0 = blockIdx.x * 128;
    if (mode == 1 && n0 >= m0 + 128) return;
    int Keff = (mode == 2) ? min(K, m0 + 128) : K;
    const int nk = Keff / 32;

    float acc[4][4][4];
#pragma unroll
    for (int i = 0; i < 4; i++)
#pragma unroll
        for (int j = 0; j < 4; j++)
#pragma unroll
            for (int f = 0; f < 4; f++) acc[i][j][f] = 0.f;

    const int la = lane >> 2, lc = lane & 3;

    // cp.async fill: 1024 16B chunks per buffer, 4 per thread per buffer
    auto issue = [&](int s, int k0) {
        const uint32_t base = sb + s * STGF;
#pragma unroll
        for (int j = 0; j < 4; j++) {
            int ci = tid + 256 * j;
            int row = ci >> 3, col = (ci & 7) * 4;
            uint32_t so = (uint32_t)(row * TSTRF + col) * 4;
            cp16(base + so, Ab + (size_t)(m0 + row) * lda + k0 + col, true);
            bool v = (n0 + row) < N;
            const float* bs = Bb + (size_t)(v ? (n0 + row) : 0) * ldb + k0 + col;
            cp16(base + BUFF + so, bs, v);
        }
    };

    issue(0, 0);
    CP_COMMIT();

    for (int it = 0; it < nk; it++) {
        if (it + 1 < nk) {
            issue((it + 1) & 1, (it + 1) * 32);
            CP_COMMIT();
            CP_WAIT(1);
        } else {
            CP_WAIT(0);
        }
        __syncthreads();

        const float* As = (const float*)(dsm + (it & 1) * STGF);
        const float* Bs = (const float*)(dsm + (it & 1) * STGF + BUFF);

#pragma unroll
        for (int k8 = 0; k8 < 4; k8++) {
            const int kc = k8 * 8;
            uint32_t bf[4][2];
#pragma unroll
            for (int nj = 0; nj < 4; nj++) {
                int n = wn * 32 + nj * 8 + la;
                bf[nj][0] = __float_as_uint(Bs[n * TSTRF + kc + lc]);
                bf[nj][1] = __float_as_uint(Bs[n * TSTRF + kc + lc + 4]);
            }
#pragma unroll
            for (int mi = 0; mi < 4; mi++) {
                int r = wm * 64 + mi * 16 + la;
                uint32_t af[4];
                af[0] = __float_as_uint(As[r * TSTRF + kc + lc]);
                af[1] = __float_as_uint(As[(r + 8) * TSTRF + kc + lc]);
                af[2] = __float_as_uint(As[r * TSTRF + kc + lc + 4]);
                af[3] = __float_as_uint(As[(r + 8) * TSTRF + kc + lc + 4]);
#pragma unroll
                for (int nj = 0; nj < 4; nj++)
                    mma_tf32(acc[mi][nj], af, bf[nj]);
            }
        }
        __syncthreads();
    }

#pragma unroll
    for (int mi = 0; mi < 4; mi++) {
        const int m1 = m0 + wm * 64 + mi * 16 + la;
        const int m2 = m1 + 8;
#pragma unroll
        for (int nj = 0; nj < 4; nj++) {
            const int n = n0 + wn * 32 + nj * 8 + lc * 2;
            if (n < N) {
                *(float2*)&Cb[(size_t)m1 * ldc + n] =
                    make_float2(alpha * acc[mi][nj][0], alpha * acc[mi][nj][1]);
                *(float2*)&Cb[(size_t)m2 * ldc + n] =
                    make_float2(alpha * acc[mi][nj][2], alpha * acc[mi][nj][3]);
            }
        }
    }
}

// ---------------- tf32 pre-round (out-of-place) ----------------
__global__ __launch_bounds__(256) void round_tf32(
    const float* __restrict__ x, float* __restrict__ o, long n)
{
    long i = (long)blockIdx.x * 256 + threadIdx.x;
    if (i < n) o[i] = rna_tf32(x[i]);
}

// ---------------- RMSNorm with tf32-rounded output ----------------
__global__ __launch_bounds__(256) void rmsnorm_round(
    const float* __restrict__ in, long ldin,
    const float* __restrict__ w,
    float* __restrict__ out, long ldout, int D)
{
    const int row = blockIdx.x;
    const float* x = in + (size_t)row * ldin;
    float* o = out + (size_t)row * ldout;

    float s = 0.f;
    for (int i = threadIdx.x; i < D; i += 256) { float v = x[i]; s += v * v; }
    __shared__ float red[8];
#pragma unroll
    for (int off = 16; off; off >>= 1) s += __shfl_xor_sync(0xffffffffu, s, off);
    if ((threadIdx.x & 31) == 0) red[threadIdx.x >> 5] = s;
    __syncthreads();
    float tot = red[0]+red[1]+red[2]+red[3]+red[4]+red[5]+red[6]+red[7];
    const float inv = rsqrtf(tot / (float)D + 1e-6f);
    for (int i = threadIdx.x; i < D; i += 256) o[i] = rna_tf32(w[i] * x[i] * inv);
}

// ---------------- RoPE table ----------------
__global__ void init_rope() {
    int j = threadIdx.x;
    if (j < 32)
        g_invf[j] = (float)exp(-((double)(2 * j) / 64.0) * log(10000.0));
}

// ---------------- fused RoPE pack -> tf32-rounded fp32 ----------------
__global__ __launch_bounds__(256) void rope_pack() {
    const int blk = blockIdx.x;          // bh*SEQ + s
    const int s  = blk % SEQ;
    const int bh = blk / SEQ;
    const int h = bh % NH, b = bh / NH;
    const long t = (long)b * SEQ + s;
    const int tid = threadIdx.x;

    float* qdst = g_qbuf + (size_t)blk * DQK;
    float* kdst = g_kbuf + (size_t)blk * DQK;
    const float* qsrc  = g_q  + t * (NH * DQK) + (long)h * DQK;
    const float* knsrc = g_kv + t * (NH * 256) + (long)h * 256;
    const float* krsrc = g_c  + t * (KVLORA + ROPE_D) + KVLORA;

    if (tid < 128) {
        qdst[tid] = rna_tf32(qsrc[tid]);
        kdst[tid] = rna_tf32(knsrc[tid]);
    } else if (tid < 160) {
        int jj = tid - 128;
        float ang = (float)s * g_invf[jj];
        float c = (float)cos((double)ang);
        float sn = (float)sin((double)ang);
        float x0 = qsrc[128 + 2 * jj];
        float x1 = qsrc[128 + 2 * jj + 1];
        qdst[128 + jj] = rna_tf32(x0 * c - x1 * sn);
        qdst[160 + jj] = rna_tf32(x1 * c + x0 * sn);
    } else if (tid < 192) {
        int jj = tid - 160;
        float ang = (float)s * g_invf[jj];
        float c = (float)cos((double)ang);
        float sn = (float)sin((double)ang);
        float x0 = krsrc[2 * jj];
        float x1 = krsrc[2 * jj + 1];
        kdst[128 + jj] = rna_tf32(x0 * c - x1 * sn);
        kdst[160 + jj] = rna_tf32(x1 * c + x0 * sn);
    }
}

// ---------------- V transpose -> tf32-rounded fp32 ----------------
__global__ __launch_bounds__(256) void vtrans() {
    long idx = (long)blockIdx.x * 256 + threadIdx.x;
    const long total = (long)BHN * DV * SEQ;
    if (idx >= total) return;
    int s = (int)(idx % SEQ);
    long r = idx / SEQ;
    int d = (int)(r % DV);
    int bh = (int)(r / DV);
    int h = bh % NH, b = bh / NH;
    g_vt[idx] = rna_tf32(g_kv[((size_t)b * SEQ + s) * (NH * 256) + (long)h * 256 + 128 + d]);
}

// ---------------- causal softmax, tf32-rounded in place ----------------
__global__ __launch_bounds__(256) void softmax_causal(float* __restrict__ attn) {
    const long r = blockIdx.x;               // bh*SEQ + q
    const int q = (int)(r % SEQ);
    float* row = attn + r * SEQ;
    const int L = q + 1;
    __shared__ float red[8];

    float mx = -3.4e38f;
    for (int k = threadIdx.x; k < L; k += 256) mx = fmaxf(mx, row[k]);
#pragma unroll
    for (int o = 16; o; o >>= 1) mx = fmaxf(mx, __shfl_xor_sync(0xffffffffu, mx, o));
    if ((threadIdx.x & 31) == 0) red[threadIdx.x >> 5] = mx;
    __syncthreads();
    mx = fmaxf(fmaxf(fmaxf(red[0], red[1]), fmaxf(red[2], red[3])),
               fmaxf(fmaxf(red[4], red[5]), fmaxf(red[6], red[7])));
    __syncthreads();

    float s = 0.f;
    for (int k = threadIdx.x; k < L; k += 256) s += expf(row[k] - mx);
#pragma unroll
    for (int o = 16; o; o >>= 1) s += __shfl_xor_sync(0xffffffffu, s, o);
    if ((threadIdx.x & 31) == 0) red[threadIdx.x >> 5] = s;
    __syncthreads();
    s = red[0]+red[1]+red[2]+red[3]+red[4]+red[5]+red[6]+red[7];
    const float inv = 1.f / s;

    for (int k = threadIdx.x; k < L; k += 256)
        row[k] = rna_tf32(expf(row[k] - mx) * inv);
    for (int k = L + (int)threadIdx.x; k < SEQ; k += 256) row[k] = 0.f;
}

// ---------------- host launch ----------------
static inline int cdiv(long a, long b) { return (int)((a + b - 1) / b); }

extern "C" void kernel_launch(void* const* d_in, const int* in_sizes, int n_in,
                              void* d_out, int out_size)
{
    const float *hs = 0, *w_q_down = 0, *q_norm_w = 0, *w_q_up = 0;
    const float *w_kv_down = 0, *kv_norm_w = 0, *w_kv_up = 0, *w_out = 0;
    for (int i = 0; i < n_in; i++) {
        long n = in_sizes[i];
        const float* ptr = (const float*)d_in[i];
        if (n == 8388608)      { if (!hs) hs = ptr; }
        else if (n == 3145728) w_q_down = ptr;
        else if (n == 1536)    q_norm_w = ptr;
        else if (n == 4718592) w_q_up = ptr;
        else if (n == 1179648) w_kv_down = ptr;
        else if (n == 512)     kv_norm_w = ptr;
        else if (n == 2097152) w_kv_up = ptr;
        else if (n == 4194304) w_out = ptr;
    }

    float* out_final = (float*)d_out;

    void* p;
    cudaGetSymbolAddress(&p, g_q1);   float* q1   = (float*)p;
    cudaGetSymbolAddress(&p, g_q1n);  float* q1n  = (float*)p;
    cudaGetSymbolAddress(&p, g_q);    float* q    = (float*)p;
    cudaGetSymbolAddress(&p, g_c);    float* c    = (float*)p;
    cudaGetSymbolAddress(&p, g_ckn);  float* ckn  = (float*)p;
    cudaGetSymbolAddress(&p, g_kv);   float* kv   = (float*)p;
    cudaGetSymbolAddress(&p, g_qbuf); float* qb   = (float*)p;
    cudaGetSymbolAddress(&p, g_kbuf); float* kb   = (float*)p;
    cudaGetSymbolAddress(&p, g_vt);   float* vt   = (float*)p;
    cudaGetSymbolAddress(&p, g_om);   float* om   = (float*)p;
    cudaGetSymbolAddress(&p, g_attn); float* attn_scratch = (float*)p;
    cudaGetSymbolAddress(&p, g_hsr);  float* hsr  = (float*)p;
    cudaGetSymbolAddress(&p, g_wqd);  float* wqd  = (float*)p;
    cudaGetSymbolAddress(&p, g_wqu);  float* wqu  = (float*)p;
    cudaGetSymbolAddress(&p, g_wkd);  float* wkd  = (float*)p;
    cudaGetSymbolAddress(&p, g_wku);  float* wku  = (float*)p;
    cudaGetSymbolAddress(&p, g_wo);   float* wo   = (float*)p;

    cudaFuncSetAttribute(mma_gemm, cudaFuncAttributeMaxDynamicSharedMemorySize, SMEMF);

    const size_t need = (size_t)TOK * HID + (size_t)BHN * SEQ * SEQ;
    float* attn_out = ((size_t)out_size >= need)
                    ? (float*)d_out + (size_t)TOK * HID
                    : attn_scratch;

    const float qk_scale = 1.0f / sqrtf((float)DQK);

    init_rope<<<1, 32>>>();

    // tf32-round the read-only inputs once
    { long n = (long)TOK*HID;              round_tf32<<<cdiv(n,256),256>>>(hs, hsr, n); }
    { long n = (long)QLORA*HID;            round_tf32<<<cdiv(n,256),256>>>(w_q_down, wqd, n); }
    { long n = (long)(NH*DQK)*QLORA;       round_tf32<<<cdiv(n,256),256>>>(w_q_up, wqu, n); }
    { long n = (long)(KVLORA+ROPE_D)*HID;  round_tf32<<<cdiv(n,256),256>>>(w_kv_down, wkd, n); }
    { long n = (long)(NH*256)*KVLORA;      round_tf32<<<cdiv(n,256),256>>>(w_kv_up, wku, n); }
    { long n = (long)HID*(NH*DV);          round_tf32<<<cdiv(n,256),256>>>(w_out, wo, n); }

    // q1 = hs @ w_q_down^T  [4096 x 1536], K=2048
    mma_gemm<<<dim3(QLORA/128, TOK/128), 256, SMEMF>>>(
        hsr, wqd, q1,
        HID, 0, HID, 0, QLORA, 0, 0, 1,
        TOK, QLORA, HID, 1.f, 0);
    rmsnorm_round<<<TOK, 256>>>(q1, QLORA, q_norm_w, q1n, QLORA, QLORA);

    // q = q1n @ w_q_up^T  [4096 x 3072], K=1536
    mma_gemm<<<dim3((NH*DQK)/128, TOK/128), 256, SMEMF>>>(
        q1n, wqu, q,
        QLORA, 0, QLORA, 0, NH*DQK, 0, 0, 1,
        TOK, NH*DQK, QLORA, 1.f, 0);

    // c = hs @ w_kv_down^T  [4096 x 576], K=2048
    mma_gemm<<<dim3(cdiv(KVLORA+ROPE_D,128), TOK/128), 256, SMEMF>>>(
        hsr, wkd, c,
        HID, 0, HID, 0, KVLORA+ROPE_D, 0, 0, 1,
        TOK, KVLORA+ROPE_D, HID, 1.f, 0);
    rmsnorm_round<<<TOK, 256>>>(c, KVLORA+ROPE_D, kv_norm_w, ckn, KVLORA, KVLORA);

    // kv = ckn @ w_kv_up^T  [4096 x 4096], K=512
    mma_gemm<<<dim3((NH*256)/128, TOK/128), 256, SMEMF>>>(
        ckn, wku, kv,
        KVLORA, 0, KVLORA, 0, NH*256, 0, 0, 1,
        TOK, NH*256, KVLORA, 1.f, 0);

    // RoPE pack of Q/K, V transpose (tf32-rounded outputs)
    rope_pack<<<BHN*SEQ, 256>>>();
    {
        long total = (long)BHN * DV * SEQ;
        vtrans<<<(int)((total + 255) / 256), 256>>>();
    }

    // scores: attn[bh] = qk_scale * Q @ K^T  (causal tile skip)
    mma_gemm<<<dim3(SEQ/128, SEQ/128, BHN), 256, SMEMF>>>(
        qb, kb, attn_out,
        DQK, (long)SEQ*DQK, DQK, (long)SEQ*DQK,
        SEQ, (long)SEQ*SEQ, 0, 1,
        SEQ, SEQ, DQK, qk_scale, 1);

    // softmax (tf32-rounded probabilities in place; PV consumes them directly)
    softmax_causal<<<BHN*SEQ, 256>>>(attn_out);

    // O = attn @ V (K clamped causally)
    mma_gemm<<<dim3(DV/128, SEQ/128, BHN), 256, SMEMF>>>(
        attn_out, vt, om,
        SEQ, (long)SEQ*SEQ, SEQ, (long)DV*SEQ,
        NH*DV, (long)SEQ*NH*DV, DV, NH,
        SEQ, DV, SEQ, 1.f, 2);

    // round om, then out = om @ w_out^T  [4096 x 2048], K=2048
    { long n = (long)TOK*(NH*DV); round_tf32<<<cdiv(n,256),256>>>(om, om, n); }
    mma_gemm<<<dim3(HID/128, TOK/128), 256, SMEMF>>>(
        om, wo, out_final,
        NH*DV, 0, NH*DV, 0, HID, 0, 0, 1,
        TOK, HID, NH*DV, 1.f, 0);
}

// round 14
// speedup vs baseline: 4.9105x; 1.0729x over previous
#include <cuda_runtime.h>
#include <cuda_bf16.h>
#include <math.h>
#include <stdint.h>

// ---------------- problem constants ----------------
#define BATCH 2
#define SEQ   2048
#define HID   2048
#define NH    16
#define DQK   192
#define DV    128
#define QLORA 1536
#define KVLORA 512
#define ROPE_D 64
#define TOK   (BATCH*SEQ)          // 4096
#define BHN   (BATCH*NH)           // 32
#define QKVD  (QLORA + KVLORA + ROPE_D)   // 2112 combined down-proj width

// ---------------- fp32 scratch (GEMM operands tf32-rounded fp32) -----
__device__ float g_qc  [(size_t)TOK * QKVD];        // combined q1|c
__device__ float g_q1n [(size_t)TOK * QLORA];
__device__ float g_q   [(size_t)TOK * (NH*DQK)];
__device__ float g_ckn [(size_t)TOK * KVLORA];
__device__ float g_kv  [(size_t)TOK * (NH*256)];
__device__ float g_qbuf[(size_t)BHN * SEQ * DQK];
__device__ float g_kbuf[(size_t)BHN * SEQ * DQK];
__device__ float g_vt  [(size_t)BHN * DV * SEQ];
__device__ float g_om  [(size_t)TOK * (NH*DV)];
__device__ float g_attn[(size_t)BHN * SEQ * SEQ];
__device__ float g_invf[32];
// rounded copies of read-only inputs
__device__ float g_hsr [(size_t)TOK*HID];
__device__ float g_wqkd[(size_t)QKVD*HID];          // concat(w_q_down, w_kv_down)
__device__ float g_wqu [(size_t)(NH*DQK)*QLORA];
__device__ float g_wku [(size_t)(NH*256)*KVLORA];
__device__ float g_wo  [(size_t)HID*(NH*DV)];

// ================= helpers =================
__device__ __forceinline__ uint32_t smem_u32(const void* p) {
    uint32_t a;
    asm("{ .reg .u64 t; cvta.to.shared.u64 t, %1; cvt.u32.u64 %0, t; }" : "=r"(a) : "l"(p));
    return a;
}
__device__ __forceinline__ float rna_tf32(float x) {
    uint32_t t; asm("cvt.rna.tf32.f32 %0, %1;" : "=r"(t) : "f"(x));
    return __uint_as_float(t);
}
__device__ __forceinline__ void mma_tf32(float* d, const uint32_t* a, const uint32_t* b) {
    asm volatile("mma.sync.aligned.m16n8k8.row.col.f32.tf32.tf32.f32 "
        "{%0,%1,%2,%3}, {%4,%5,%6,%7}, {%8,%9}, {%0,%1,%2,%3};"
        : "+f"(d[0]), "+f"(d[1]), "+f"(d[2]), "+f"(d[3])
        : "r"(a[0]), "r"(a[1]), "r"(a[2]), "r"(a[3]), "r"(b[0]), "r"(b[1]));
}
__device__ __forceinline__ void cp16(uint32_t dst, const void* src, bool v) {
    int sz = v ? 16 : 0;
    asm volatile("cp.async.cg.shared.global [%0], [%1], 16, %2;"
        :: "r"(dst), "l"(src), "r"(sz) : "memory");
}
#define CP_COMMIT() asm volatile("cp.async.commit_group;" ::: "memory")
#define CP_WAIT(n)  asm volatile("cp.async.wait_group %0;" :: "n"(n) : "memory")

// ---------------- batched single-pass TF32 tensor GEMM, cp.async 3-stage --
// C = alpha * A * B^T   (A,B fp32 pre-rounded to tf32; fp32 accumulate)
// mode 0 plain; 1 causal: skip tiles above diagonal but ZERO-FILL them;
// mode 2 K clamped to m0+128.  rndC: round C to tf32 in epilogue.
#define TSTRF 36                   // smem row stride in floats
#define BUFF (128*TSTRF*4)         // 18432 B per tile buffer
#define STGF (2*BUFF)              // 36864 B per stage
#define SMEMF (3*STGF)             // 110592 B (3 stages)

__global__ __launch_bounds__(256, 2) void mma_gemm(
    const float* __restrict__ A, const float* __restrict__ B,
    float* __restrict__ C,
    long lda, long sA, long ldb, long sB,
    long ldc, long sC, long sC2, int zdiv,
    int M, int N, int K, float alpha, int mode, int rndC)
{
    extern __shared__ char dsm[];
    const uint32_t sb = smem_u32(dsm);

    const int z = blockIdx.z;
    float* Cb = C + (size_t)(z / zdiv) * sC + (size_t)(z % zdiv) * sC2;

    const int tid = threadIdx.x;
    const int m0 = blockIdx.y * 128, n0 = blockIdx.x * 128;

    if (mode == 1 && n0 >= m0 + 128) {
        // strictly-above-diagonal tile: write zeros (attn output needs them)
        const float4 z4 = make_float4(0.f, 0.f, 0.f, 0.f);
#pragma unroll
        for (int i = 0; i < 16; i++) {
            int idx = i * 256 + tid;           // 4096 float4 slots = 128x128
            int row = idx >> 5, col = (idx & 31) * 4;
            *(float4*)&Cb[(size_t)(m0 + row) * ldc + n0 + col] = z4;
        }
        return;
    }

    const float* Ab = A + (size_t)z * sA;
    const float* Bb = B + (size_t)z * sB;

    const int lane = tid & 31;
    const int wid = tid >> 5;
    const int wm = wid >> 2;
    const int wn = wid & 3;
    int Keff = (mode == 2) ? min(K, m0 + 128) : K;
    const int nk = Keff / 32;

    float acc[4][4][4];
#pragma unroll
    for (int i = 0; i < 4; i++)
#pragma unroll
        for (int j = 0; j < 4; j++)
#pragma unroll
            for (int f = 0; f < 4; f++) acc[i][j][f] = 0.f;

    const int la = lane >> 2, lc = lane & 3;

    auto issue = [&](int s, int k0) {
        const uint32_t base = sb + s * STGF;
#pragma unroll
        for (int j = 0; j < 4; j++) {
            int ci = tid + 256 * j;
            int row = ci >> 3, col = (ci & 7) * 4;
            uint32_t so = (uint32_t)(row * TSTRF + col) * 4;
            cp16(base + so, Ab + (size_t)(m0 + row) * lda + k0 + col, true);
            bool v = (n0 + row) < N;
            const float* bs = Bb + (size_t)(v ? (n0 + row) : 0) * ldb + k0 + col;
            cp16(base + BUFF + so, bs, v);
        }
    };

    issue(0, 0);
    CP_COMMIT();
    if (nk > 1) { issue(1, 32); CP_COMMIT(); }

    for (int it = 0; it < nk; it++) {
        if (it + 2 < nk) {
            issue((it + 2) % 3, (it + 2) * 32);
            CP_COMMIT();
            CP_WAIT(2);
        } else if (it + 1 < nk) {
            CP_WAIT(1);
        } else {
            CP_WAIT(0);
        }
        __syncthreads();

        const float* As = (const float*)(dsm + (it % 3) * STGF);
        const float* Bs = (const float*)(dsm + (it % 3) * STGF + BUFF);

#pragma unroll
        for (int k8 = 0; k8 < 4; k8++) {
            const int kc = k8 * 8;
            uint32_t bf[4][2];
#pragma unroll
            for (int nj = 0; nj < 4; nj++) {
                int n = wn * 32 + nj * 8 + la;
                bf[nj][0] = __float_as_uint(Bs[n * TSTRF + kc + lc]);
                bf[nj][1] = __float_as_uint(Bs[n * TSTRF + kc + lc + 4]);
            }
#pragma unroll
            for (int mi = 0; mi < 4; mi++) {
                int r = wm * 64 + mi * 16 + la;
                uint32_t af[4];
                af[0] = __float_as_uint(As[r * TSTRF + kc + lc]);
                af[1] = __float_as_uint(As[(r + 8) * TSTRF + kc + lc]);
                af[2] = __float_as_uint(As[r * TSTRF + kc + lc + 4]);
                af[3] = __float_as_uint(As[(r + 8) * TSTRF + kc + lc + 4]);
#pragma unroll
                for (int nj = 0; nj < 4; nj++)
                    mma_tf32(acc[mi][nj], af, bf[nj]);
            }
        }
        __syncthreads();
    }

#pragma unroll
    for (int mi = 0; mi < 4; mi++) {
        const int m1 = m0 + wm * 64 + mi * 16 + la;
        const int m2 = m1 + 8;
#pragma unroll
        for (int nj = 0; nj < 4; nj++) {
            const int n = n0 + wn * 32 + nj * 8 + lc * 2;
            if (n < N) {
                float v0 = alpha * acc[mi][nj][0], v1 = alpha * acc[mi][nj][1];
                float v2 = alpha * acc[mi][nj][2], v3 = alpha * acc[mi][nj][3];
                if (rndC) { v0 = rna_tf32(v0); v1 = rna_tf32(v1); v2 = rna_tf32(v2); v3 = rna_tf32(v3); }
                *(float2*)&Cb[(size_t)m1 * ldc + n] = make_float2(v0, v1);
                *(float2*)&Cb[(size_t)m2 * ldc + n] = make_float2(v2, v3);
            }
        }
    }
}

// ---------------- vectorized tf32 pre-round ----------------
__global__ __launch_bounds__(256) void round4(
    const float4* __restrict__ x, float4* __restrict__ o, long n4)
{
    long i = (long)blockIdx.x * 256 + threadIdx.x;
    if (i >= n4) return;
    float4 v = x[i];
    v.x = rna_tf32(v.x); v.y = rna_tf32(v.y);
    v.z = rna_tf32(v.z); v.w = rna_tf32(v.w);
    o[i] = v;
}

// ---------------- RMSNorm with tf32-rounded output ----------------
__global__ __launch_bounds__(256) void rmsnorm_round(
    const float* __restrict__ in, long ldin,
    const float* __restrict__ w,
    float* __restrict__ out, long ldout, int D)
{
    const int row = blockIdx.x;
    const float* x = in + (size_t)row * ldin;
    float* o = out + (size_t)row * ldout;

    float s = 0.f;
    for (int i = threadIdx.x; i < D; i += 256) { float v = x[i]; s += v * v; }
    __shared__ float red[8];
#pragma unroll
    for (int off = 16; off; off >>= 1) s += __shfl_xor_sync(0xffffffffu, s, off);
    if ((threadIdx.x & 31) == 0) red[threadIdx.x >> 5] = s;
    __syncthreads();
    float tot = red[0]+red[1]+red[2]+red[3]+red[4]+red[5]+red[6]+red[7];
    const float inv = rsqrtf(tot / (float)D + 1e-6f);
    for (int i = threadIdx.x; i < D; i += 256) o[i] = rna_tf32(w[i] * x[i] * inv);
}

// ---------------- RoPE table ----------------
__global__ void init_rope() {
    int j = threadIdx.x;
    if (j < 32)
        g_invf[j] = (float)exp(-((double)(2 * j) / 64.0) * log(10000.0));
}

// ---------------- fused RoPE pack -> tf32-rounded fp32 ----------------
__global__ __launch_bounds__(256) void rope_pack() {
    const int blk = blockIdx.x;          // bh*SEQ + s
    const int s  = blk % SEQ;
    const int bh = blk / SEQ;
    const int h = bh % NH, b = bh / NH;
    const long t = (long)b * SEQ + s;
    const int tid = threadIdx.x;

    float* qdst = g_qbuf + (size_t)blk * DQK;
    float* kdst = g_kbuf + (size_t)blk * DQK;
    const float* qsrc  = g_q  + t * (NH * DQK) + (long)h * DQK;
    const float* knsrc = g_kv + t * (NH * 256) + (long)h * 256;
    const float* krsrc = g_qc + t * QKVD + QLORA + KVLORA;   // rope part of c

    if (tid < 128) {
        qdst[tid] = rna_tf32(qsrc[tid]);
        kdst[tid] = rna_tf32(knsrc[tid]);
    } else if (tid < 160) {
        int jj = tid - 128;
        float ang = (float)s * g_invf[jj];
        float c = (float)cos((double)ang);
        float sn = (float)sin((double)ang);
        float x0 = qsrc[128 + 2 * jj];
        float x1 = qsrc[128 + 2 * jj + 1];
        qdst[128 + jj] = rna_tf32(x0 * c - x1 * sn);
        qdst[160 + jj] = rna_tf32(x1 * c + x0 * sn);
    } else if (tid < 192) {
        int jj = tid - 160;
        float ang = (float)s * g_invf[jj];
        float c = (float)cos((double)ang);
        float sn = (float)sin((double)ang);
        float x0 = krsrc[2 * jj];
        float x1 = krsrc[2 * jj + 1];
        kdst[128 + jj] = rna_tf32(x0 * c - x1 * sn);
        kdst[160 + jj] = rna_tf32(x1 * c + x0 * sn);
    }
}

// ---------------- V transpose -> tf32-rounded fp32 ----------------
__global__ __launch_bounds__(256) void vtrans() {
    long idx = (long)blockIdx.x * 256 + threadIdx.x;
    const long total = (long)BHN * DV * SEQ;
    if (idx >= total) return;
    int s = (int)(idx % SEQ);
    long r = idx / SEQ;
    int d = (int)(r % DV);
    int bh = (int)(r / DV);
    int h = bh % NH, b = bh / NH;
    g_vt[idx] = rna_tf32(g_kv[((size_t)b * SEQ + s) * (NH * 256) + (long)h * 256 + 128 + d]);
}

// ---------------- causal softmax: smem-cached, writes [0, Lc) only -------
// Cols >= Lc (128-aligned causal bound) already zero-filled by scores GEMM.
__global__ __launch_bounds__(256) void softmax_causal(float* __restrict__ attn) {
    const long r = blockIdx.x;               // bh*SEQ + q
    const int q = (int)(r % SEQ);
    float* row = attn + r * SEQ;
    const int L = q + 1;
    const int Lc = (L + 127) & ~127;
    const int L4 = L & ~3;

    __shared__ float sh[SEQ];
    __shared__ float red[8];

    float mx = -3.4e38f;
    for (int k = threadIdx.x * 4; k < L4; k += 1024) {
        float4 v = *(const float4*)&row[k];
        *(float4*)&sh[k] = v;
        mx = fmaxf(fmaxf(mx, fmaxf(v.x, v.y)), fmaxf(v.z, v.w));
    }
    for (int k = L4 + threadIdx.x; k < L; k += 256) {
        float v = row[k]; sh[k] = v; mx = fmaxf(mx, v);
    }
#pragma unroll
    for (int o = 16; o; o >>= 1) mx = fmaxf(mx, __shfl_xor_sync(0xffffffffu, mx, o));
    if ((threadIdx.x & 31) == 0) red[threadIdx.x >> 5] = mx;
    __syncthreads();
    mx = fmaxf(fmaxf(fmaxf(red[0], red[1]), fmaxf(red[2], red[3])),
               fmaxf(fmaxf(red[4], red[5]), fmaxf(red[6], red[7])));
    __syncthreads();

    float s = 0.f;
    for (int k = threadIdx.x; k < L; k += 256) {
        float e = expf(sh[k] - mx);
        sh[k] = e;
        s += e;
    }
#pragma unroll
    for (int o = 16; o; o >>= 1) s += __shfl_xor_sync(0xffffffffu, s, o);
    if ((threadIdx.x & 31) == 0) red[threadIdx.x >> 5] = s;
    __syncthreads();
    s = red[0]+red[1]+red[2]+red[3]+red[4]+red[5]+red[6]+red[7];
    const float inv = 1.f / s;
    __syncthreads();

    for (int k = threadIdx.x * 4; k < L4; k += 1024) {
        float4 v = *(const float4*)&sh[k];
        v.x = rna_tf32(v.x * inv); v.y = rna_tf32(v.y * inv);
        v.z = rna_tf32(v.z * inv); v.w = rna_tf32(v.w * inv);
        *(float4*)&row[k] = v;
    }
    for (int k = L4 + threadIdx.x; k < L; k += 256)
        row[k] = rna_tf32(sh[k] * inv);
    for (int k = L + threadIdx.x; k < Lc; k += 256)
        row[k] = 0.f;
}

// ---------------- host launch ----------------
static inline int cdiv(long a, long b) { return (int)((a + b - 1) / b); }

extern "C" void kernel_launch(void* const* d_in, const int* in_sizes, int n_in,
                              void* d_out, int out_size)
{
    const float *hs = 0, *w_q_down = 0, *q_norm_w = 0, *w_q_up = 0;
    const float *w_kv_down = 0, *kv_norm_w = 0, *w_kv_up = 0, *w_out = 0;
    for (int i = 0; i < n_in; i++) {
        long n = in_sizes[i];
        const float* ptr = (const float*)d_in[i];
        if (n == 8388608)      { if (!hs) hs = ptr; }
        else if (n == 3145728) w_q_down = ptr;
        else if (n == 1536)    q_norm_w = ptr;
        else if (n == 4718592) w_q_up = ptr;
        else if (n == 1179648) w_kv_down = ptr;
        else if (n == 512)     kv_norm_w = ptr;
        else if (n == 2097152) w_kv_up = ptr;
        else if (n == 4194304) w_out = ptr;
    }

    float* out_final = (float*)d_out;

    void* p;
    cudaGetSymbolAddress(&p, g_qc);   float* qc   = (float*)p;
    cudaGetSymbolAddress(&p, g_q1n);  float* q1n  = (float*)p;
    cudaGetSymbolAddress(&p, g_q);    float* q    = (float*)p;
    cudaGetSymbolAddress(&p, g_ckn);  float* ckn  = (float*)p;
    cudaGetSymbolAddress(&p, g_kv);   float* kv   = (float*)p;
    cudaGetSymbolAddress(&p, g_qbuf); float* qb   = (float*)p;
    cudaGetSymbolAddress(&p, g_kbuf); float* kb   = (float*)p;
    cudaGetSymbolAddress(&p, g_vt);   float* vt   = (float*)p;
    cudaGetSymbolAddress(&p, g_om);   float* om   = (float*)p;
    cudaGetSymbolAddress(&p, g_attn); float* attn_scratch = (float*)p;
    cudaGetSymbolAddress(&p, g_hsr);  float* hsr  = (float*)p;
    cudaGetSymbolAddress(&p, g_wqkd); float* wqkd = (float*)p;
    cudaGetSymbolAddress(&p, g_wqu);  float* wqu  = (float*)p;
    cudaGetSymbolAddress(&p, g_wku);  float* wku  = (float*)p;
    cudaGetSymbolAddress(&p, g_wo);   float* wo   = (float*)p;

    cudaFuncSetAttribute(mma_gemm, cudaFuncAttributeMaxDynamicSharedMemorySize, SMEMF);

    const size_t need = (size_t)TOK * HID + (size_t)BHN * SEQ * SEQ;
    float* attn_out = ((size_t)out_size >= need)
                    ? (float*)d_out + (size_t)TOK * HID
                    : attn_scratch;

    const float qk_scale = 1.0f / sqrtf((float)DQK);

    init_rope<<<1, 32>>>();

    // tf32-round the read-only inputs once (vectorized)
    { long n4 = (long)TOK*HID/4;              round4<<<cdiv(n4,256),256>>>((const float4*)hs, (float4*)hsr, n4); }
    { long n4 = (long)QLORA*HID/4;            round4<<<cdiv(n4,256),256>>>((const float4*)w_q_down, (float4*)wqkd, n4); }
    { long n4 = (long)(KVLORA+ROPE_D)*HID/4;  round4<<<cdiv(n4,256),256>>>((const float4*)w_kv_down, (float4*)(wqkd + (size_t)QLORA*HID), n4); }
    { long n4 = (long)(NH*DQK)*QLORA/4;       round4<<<cdiv(n4,256),256>>>((const float4*)w_q_up, (float4*)wqu, n4); }
    { long n4 = (long)(NH*256)*KVLORA/4;      round4<<<cdiv(n4,256),256>>>((const float4*)w_kv_up, (float4*)wku, n4); }
    { long n4 = (long)HID*(NH*DV)/4;          round4<<<cdiv(n4,256),256>>>((const float4*)w_out, (float4*)wo, n4); }

    // qc = hs @ concat(w_q_down, w_kv_down)^T  [4096 x 2112], K=2048
    mma_gemm<<<dim3(cdiv(QKVD,128), TOK/128), 256, SMEMF>>>(
        hsr, wqkd, qc,
        HID, 0, HID, 0, QKVD, 0, 0, 1,
        TOK, QKVD, HID, 1.f, 0, 0);
    rmsnorm_round<<<TOK, 256>>>(qc, QKVD, q_norm_w, q1n, QLORA, QLORA);
    rmsnorm_round<<<TOK, 256>>>(qc + QLORA, QKVD, kv_norm_w, ckn, KVLORA, KVLORA);

    // q = q1n @ w_q_up^T  [4096 x 3072], K=1536
    mma_gemm<<<dim3((NH*DQK)/128, TOK/128), 256, SMEMF>>>(
        q1n, wqu, q,
        QLORA, 0, QLORA, 0, NH*DQK, 0, 0, 1,
        TOK, NH*DQK, QLORA, 1.f, 0, 0);

    // kv = ckn @ w_kv_up^T  [4096 x 4096], K=512
    mma_gemm<<<dim3((NH*256)/128, TOK/128), 256, SMEMF>>>(
        ckn, wku, kv,
        KVLORA, 0, KVLORA, 0, NH*256, 0, 0, 1,
        TOK, NH*256, KVLORA, 1.f, 0, 0);

    // RoPE pack of Q/K, V transpose
    rope_pack<<<BHN*SEQ, 256>>>();
    {
        long total = (long)BHN * DV * SEQ;
        vtrans<<<(int)((total + 255) / 256), 256>>>();
    }

    // scores: attn[bh] = qk_scale * Q @ K^T  (causal; skipped tiles zero-filled)
    mma_gemm<<<dim3(SEQ/128, SEQ/128, BHN), 256, SMEMF>>>(
        qb, kb, attn_out,
        DQK, (long)SEQ*DQK, DQK, (long)SEQ*DQK,
        SEQ, (long)SEQ*SEQ, 0, 1,
        SEQ, SEQ, DQK, qk_scale, 1, 0);

    // softmax (tf32-rounded probabilities; writes only [0, Lc))
    softmax_causal<<<BHN*SEQ, 256>>>(attn_out);

    // O = attn @ V (K clamped causally), epilogue rounds om to tf32
    mma_gemm<<<dim3(DV/128, SEQ/128, BHN), 256, SMEMF>>>(
        attn_out, vt, om,
        SEQ, (long)SEQ*SEQ, SEQ, (long)DV*SEQ,
        NH*DV, (long)SEQ*NH*DV, DV, NH,
        SEQ, DV, SEQ, 1.f, 2, 1);

    // out = om @ w_out^T  [4096 x 2048], K=2048
    mma_gemm<<<dim3(HID/128, TOK/128), 256, SMEMF>>>(
        om, wo, out_final,
        NH*DV, 0, NH*DV, 0, HID, 0, 0, 1,
        TOK, HID, NH*DV, 1.f, 0, 0);
}

// round 15
// speedup vs baseline: 5.1874x; 1.0564x over previous
#include <cuda_runtime.h>
#include <cuda_bf16.h>
#include <math.h>
#include <stdint.h>

// ---------------- problem constants ----------------
#define BATCH 2
#define SEQ   2048
#define HID   2048
#define NH    16
#define DQK   192
#define DV    128
#define QLORA 1536
#define KVLORA 512
#define ROPE_D 64
#define TOK   (BATCH*SEQ)          // 4096
#define BHN   (BATCH*NH)           // 32
#define QKVD  (QLORA + KVLORA + ROPE_D)   // 2112

// ---------------- fp32 scratch ----------------
__device__ float g_qc  [(size_t)TOK * QKVD];
__device__ float g_q1n [(size_t)TOK * QLORA];
__device__ float g_q   [(size_t)TOK * (NH*DQK)];
__device__ float g_ckn [(size_t)TOK * KVLORA];
__device__ float g_kv  [(size_t)TOK * (NH*256)];
__device__ float g_qbuf[(size_t)BHN * SEQ * DQK];
__device__ float g_kbuf[(size_t)BHN * SEQ * DQK];
__device__ float g_vt  [(size_t)BHN * DV * SEQ];
__device__ float g_om  [(size_t)TOK * (NH*DV)];
__device__ float g_attn[(size_t)BHN * SEQ * SEQ];
__device__ float g_invf[32];
__device__ float g_hsr [(size_t)TOK*HID];
__device__ float g_wqkd[(size_t)QKVD*HID];
__device__ float g_wqu [(size_t)(NH*DQK)*QLORA];
__device__ float g_wku [(size_t)(NH*256)*KVLORA];
__device__ float g_wo  [(size_t)HID*(NH*DV)];

// ================= helpers =================
__device__ __forceinline__ uint32_t smem_u32(const void* p) {
    uint32_t a;
    asm("{ .reg .u64 t; cvta.to.shared.u64 t, %1; cvt.u32.u64 %0, t; }" : "=r"(a) : "l"(p));
    return a;
}
__device__ __forceinline__ float rna_tf32(float x) {
    uint32_t t; asm("cvt.rna.tf32.f32 %0, %1;" : "=r"(t) : "f"(x));
    return __uint_as_float(t);
}
__device__ __forceinline__ void mma_tf32(float* d, const uint32_t* a, const uint32_t* b) {
    asm volatile("mma.sync.aligned.m16n8k8.row.col.f32.tf32.tf32.f32 "
        "{%0,%1,%2,%3}, {%4,%5,%6,%7}, {%8,%9}, {%0,%1,%2,%3};"
        : "+f"(d[0]), "+f"(d[1]), "+f"(d[2]), "+f"(d[3])
        : "r"(a[0]), "r"(a[1]), "r"(a[2]), "r"(a[3]), "r"(b[0]), "r"(b[1]));
}
__device__ __forceinline__ void cp16(uint32_t dst, const void* src, bool v) {
    int sz = v ? 16 : 0;
    asm volatile("cp.async.cg.shared.global [%0], [%1], 16, %2;"
        :: "r"(dst), "l"(src), "r"(sz) : "memory");
}
#define CP_COMMIT() asm volatile("cp.async.commit_group;" ::: "memory")
#define CP_WAIT(n)  asm volatile("cp.async.wait_group %0;" :: "n"(n) : "memory")

// ---------------- batched single-pass TF32 tensor GEMM, cp.async 3-stage --
#define TSTRF 36
#define BUFF (128*TSTRF*4)
#define STGF (2*BUFF)
#define SMEMF (3*STGF)

__global__ __launch_bounds__(256, 2) void mma_gemm(
    const float* __restrict__ A, const float* __restrict__ B,
    float* __restrict__ C,
    long lda, long sA, long ldb, long sB,
    long ldc, long sC, long sC2, int zdiv,
    int M, int N, int K, float alpha, int mode, int rndC)
{
    extern __shared__ char dsm[];
    const uint32_t sb = smem_u32(dsm);

    const int z = blockIdx.z;
    float* Cb = C + (size_t)(z / zdiv) * sC + (size_t)(z % zdiv) * sC2;

    const int tid = threadIdx.x;
    const int m0 = blockIdx.y * 128, n0 = blockIdx.x * 128;

    if (mode == 1 && n0 >= m0 + 128) {
        const float4 z4 = make_float4(0.f, 0.f, 0.f, 0.f);
#pragma unroll
        for (int i = 0; i < 16; i++) {
            int idx = i * 256 + tid;
            int row = idx >> 5, col = (idx & 31) * 4;
            *(float4*)&Cb[(size_t)(m0 + row) * ldc + n0 + col] = z4;
        }
        return;
    }

    const float* Ab = A + (size_t)z * sA;
    const float* Bb = B + (size_t)z * sB;

    const int lane = tid & 31;
    const int wid = tid >> 5;
    const int wm = wid >> 2;
    const int wn = wid & 3;
    int Keff = (mode == 2) ? min(K, m0 + 128) : K;
    const int nk = Keff / 32;

    float acc[4][4][4];
#pragma unroll
    for (int i = 0; i < 4; i++)
#pragma unroll
        for (int j = 0; j < 4; j++)
#pragma unroll
            for (int f = 0; f < 4; f++) acc[i][j][f] = 0.f;

    const int la = lane >> 2, lc = lane & 3;
    // hoisted smem element offsets (in floats)
    const int boff = (wn * 32 + la) * TSTRF + lc;
    const int aoff = (wm * 64 + la) * TSTRF + lc;

    auto issue = [&](int s, int k0) {
        const uint32_t base = sb + s * STGF;
#pragma unroll
        for (int j = 0; j < 4; j++) {
            int ci = tid + 256 * j;
            int row = ci >> 3, col = (ci & 7) * 4;
            uint32_t so = (uint32_t)(row * TSTRF + col) * 4;
            cp16(base + so, Ab + (size_t)(m0 + row) * lda + k0 + col, true);
            bool v = (n0 + row) < N;
            const float* bs = Bb + (size_t)(v ? (n0 + row) : 0) * ldb + k0 + col;
            cp16(base + BUFF + so, bs, v);
        }
    };

    issue(0, 0);
    CP_COMMIT();
    if (nk > 1) { issue(1, 32); CP_COMMIT(); }

    for (int it = 0; it < nk; it++) {
        if (it + 2 < nk) {
            issue((it + 2) % 3, (it + 2) * 32);
            CP_COMMIT();
            CP_WAIT(2);
        } else if (it + 1 < nk) {
            CP_WAIT(1);
        } else {
            CP_WAIT(0);
        }
        __syncthreads();

        const float* As = (const float*)(dsm + (it % 3) * STGF);
        const float* Bs = (const float*)(dsm + (it % 3) * STGF + BUFF);

#pragma unroll
        for (int k8 = 0; k8 < 4; k8++) {
            const int kc = k8 * 8;
            uint32_t bf[4][2];
#pragma unroll
            for (int nj = 0; nj < 4; nj++) {
                const float* bp = Bs + boff + nj * 8 * TSTRF + kc;
                bf[nj][0] = __float_as_uint(bp[0]);
                bf[nj][1] = __float_as_uint(bp[4]);
            }
#pragma unroll
            for (int mi = 0; mi < 4; mi++) {
                const float* ap = As + aoff + mi * 16 * TSTRF + kc;
                uint32_t af[4];
                af[0] = __float_as_uint(ap[0]);
                af[1] = __float_as_uint(ap[8 * TSTRF]);
                af[2] = __float_as_uint(ap[4]);
                af[3] = __float_as_uint(ap[8 * TSTRF + 4]);
#pragma unroll
                for (int nj = 0; nj < 4; nj++)
                    mma_tf32(acc[mi][nj], af, bf[nj]);
            }
        }
        __syncthreads();
    }

#pragma unroll
    for (int mi = 0; mi < 4; mi++) {
        const int m1 = m0 + wm * 64 + mi * 16 + la;
        const int m2 = m1 + 8;
#pragma unroll
        for (int nj = 0; nj < 4; nj++) {
            const int n = n0 + wn * 32 + nj * 8 + lc * 2;
            if (n < N) {
                float v0 = alpha * acc[mi][nj][0], v1 = alpha * acc[mi][nj][1];
                float v2 = alpha * acc[mi][nj][2], v3 = alpha * acc[mi][nj][3];
                if (rndC) { v0 = rna_tf32(v0); v1 = rna_tf32(v1); v2 = rna_tf32(v2); v3 = rna_tf32(v3); }
                *(float2*)&Cb[(size_t)m1 * ldc + n] = make_float2(v0, v1);
                *(float2*)&Cb[(size_t)m2 * ldc + n] = make_float2(v2, v3);
            }
        }
    }
}

// ---------------- vectorized tf32 pre-round ----------------
__global__ __launch_bounds__(256) void round4(
    const float4* __restrict__ x, float4* __restrict__ o, long n4)
{
    long i = (long)blockIdx.x * 256 + threadIdx.x;
    if (i >= n4) return;
    float4 v = x[i];
    v.x = rna_tf32(v.x); v.y = rna_tf32(v.y);
    v.z = rna_tf32(v.z); v.w = rna_tf32(v.w);
    o[i] = v;
}

// ---------------- RMSNorm with tf32-rounded output ----------------
__global__ __launch_bounds__(256) void rmsnorm_round(
    const float* __restrict__ in, long ldin,
    const float* __restrict__ w,
    float* __restrict__ out, long ldout, int D)
{
    const int row = blockIdx.x;
    const float* x = in + (size_t)row * ldin;
    float* o = out + (size_t)row * ldout;

    float s = 0.f;
    for (int i = threadIdx.x; i < D; i += 256) { float v = x[i]; s += v * v; }
    __shared__ float red[8];
#pragma unroll
    for (int off = 16; off; off >>= 1) s += __shfl_xor_sync(0xffffffffu, s, off);
    if ((threadIdx.x & 31) == 0) red[threadIdx.x >> 5] = s;
    __syncthreads();
    float tot = red[0]+red[1]+red[2]+red[3]+red[4]+red[5]+red[6]+red[7];
    const float inv = rsqrtf(tot / (float)D + 1e-6f);
    for (int i = threadIdx.x; i < D; i += 256) o[i] = rna_tf32(w[i] * x[i] * inv);
}

// ---------------- RoPE table ----------------
__global__ void init_rope() {
    int j = threadIdx.x;
    if (j < 32)
        g_invf[j] = (float)exp(-((double)(2 * j) / 64.0) * log(10000.0));
}

// ---------------- fused RoPE pack ----------------
__global__ __launch_bounds__(256) void rope_pack() {
    const int blk = blockIdx.x;
    const int s  = blk % SEQ;
    const int bh = blk / SEQ;
    const int h = bh % NH, b = bh / NH;
    const long t = (long)b * SEQ + s;
    const int tid = threadIdx.x;

    float* qdst = g_qbuf + (size_t)blk * DQK;
    float* kdst = g_kbuf + (size_t)blk * DQK;
    const float* qsrc  = g_q  + t * (NH * DQK) + (long)h * DQK;
    const float* knsrc = g_kv + t * (NH * 256) + (long)h * 256;
    const float* krsrc = g_qc + t * QKVD + QLORA + KVLORA;

    if (tid < 128) {
        qdst[tid] = rna_tf32(qsrc[tid]);
        kdst[tid] = rna_tf32(knsrc[tid]);
    } else if (tid < 160) {
        int jj = tid - 128;
        float ang = (float)s * g_invf[jj];
        float c = (float)cos((double)ang);
        float sn = (float)sin((double)ang);
        float x0 = qsrc[128 + 2 * jj];
        float x1 = qsrc[128 + 2 * jj + 1];
        qdst[128 + jj] = rna_tf32(x0 * c - x1 * sn);
        qdst[160 + jj] = rna_tf32(x1 * c + x0 * sn);
    } else if (tid < 192) {
        int jj = tid - 160;
        float ang = (float)s * g_invf[jj];
        float c = (float)cos((double)ang);
        float sn = (float)sin((double)ang);
        float x0 = krsrc[2 * jj];
        float x1 = krsrc[2 * jj + 1];
        kdst[128 + jj] = rna_tf32(x0 * c - x1 * sn);
        kdst[160 + jj] = rna_tf32(x1 * c + x0 * sn);
    }
}

// ---------------- V transpose ----------------
__global__ __launch_bounds__(256) void vtrans() {
    long idx = (long)blockIdx.x * 256 + threadIdx.x;
    const long total = (long)BHN * DV * SEQ;
    if (idx >= total) return;
    int s = (int)(idx % SEQ);
    long r = idx / SEQ;
    int d = (int)(r % DV);
    int bh = (int)(r / DV);
    int h = bh % NH, b = bh / NH;
    g_vt[idx] = rna_tf32(g_kv[((size_t)b * SEQ + s) * (NH * 256) + (long)h * 256 + 128 + d]);
}

// ---------------- causal softmax ----------------
__global__ __launch_bounds__(256) void softmax_causal(float* __restrict__ attn) {
    const long r = blockIdx.x;
    const int q = (int)(r % SEQ);
    float* row = attn + r * SEQ;
    const int L = q + 1;
    const int Lc = (L + 127) & ~127;
    const int L4 = L & ~3;

    __shared__ float sh[SEQ];
    __shared__ float red[8];

    float mx = -3.4e38f;
    for (int k = threadIdx.x * 4; k < L4; k += 1024) {
        float4 v = *(const float4*)&row[k];
        *(float4*)&sh[k] = v;
        mx = fmaxf(fmaxf(mx, fmaxf(v.x, v.y)), fmaxf(v.z, v.w));
    }
    for (int k = L4 + threadIdx.x; k < L; k += 256) {
        float v = row[k]; sh[k] = v; mx = fmaxf(mx, v);
    }
#pragma unroll
    for (int o = 16; o; o >>= 1) mx = fmaxf(mx, __shfl_xor_sync(0xffffffffu, mx, o));
    if ((threadIdx.x & 31) == 0) red[threadIdx.x >> 5] = mx;
    __syncthreads();
    mx = fmaxf(fmaxf(fmaxf(red[0], red[1]), fmaxf(red[2], red[3])),
               fmaxf(fmaxf(red[4], red[5]), fmaxf(red[6], red[7])));
    __syncthreads();

    float s = 0.f;
    for (int k = threadIdx.x; k < L; k += 256) {
        float e = expf(sh[k] - mx);
        sh[k] = e;
        s += e;
    }
#pragma unroll
    for (int o = 16; o; o >>= 1) s += __shfl_xor_sync(0xffffffffu, s, o);
    if ((threadIdx.x & 31) == 0) red[threadIdx.x >> 5] = s;
    __syncthreads();
    s = red[0]+red[1]+red[2]+red[3]+red[4]+red[5]+red[6]+red[7];
    const float inv = 1.f / s;
    __syncthreads();

    for (int k = threadIdx.x * 4; k < L4; k += 1024) {
        float4 v = *(const float4*)&sh[k];
        v.x = rna_tf32(v.x * inv); v.y = rna_tf32(v.y * inv);
        v.z = rna_tf32(v.z * inv); v.w = rna_tf32(v.w * inv);
        *(float4*)&row[k] = v;
    }
    for (int k = L4 + threadIdx.x; k < L; k += 256)
        row[k] = rna_tf32(sh[k] * inv);
    for (int k = L + threadIdx.x; k < Lc; k += 256)
        row[k] = 0.f;
}

// ---------------- host launch ----------------
static inline int cdiv(long a, long b) { return (int)((a + b - 1) / b); }

extern "C" void kernel_launch(void* const* d_in, const int* in_sizes, int n_in,
                              void* d_out, int out_size)
{
    const float *hs = 0, *w_q_down = 0, *q_norm_w = 0, *w_q_up = 0;
    const float *w_kv_down = 0, *kv_norm_w = 0, *w_kv_up = 0, *w_out = 0;
    for (int i = 0; i < n_in; i++) {
        long n = in_sizes[i];
        const float* ptr = (const float*)d_in[i];
        if (n == 8388608)      { if (!hs) hs = ptr; }
        else if (n == 3145728) w_q_down = ptr;
        else if (n == 1536)    q_norm_w = ptr;
        else if (n == 4718592) w_q_up = ptr;
        else if (n == 1179648) w_kv_down = ptr;
        else if (n == 512)     kv_norm_w = ptr;
        else if (n == 2097152) w_kv_up = ptr;
        else if (n == 4194304) w_out = ptr;
    }

    float* out_final = (float*)d_out;

    void* p;
    cudaGetSymbolAddress(&p, g_qc);   float* qc   = (float*)p;
    cudaGetSymbolAddress(&p, g_q1n);  float* q1n  = (float*)p;
    cudaGetSymbolAddress(&p, g_q);    float* q    = (float*)p;
    cudaGetSymbolAddress(&p, g_ckn);  float* ckn  = (float*)p;
    cudaGetSymbolAddress(&p, g_kv);   float* kv   = (float*)p;
    cudaGetSymbolAddress(&p, g_qbuf); float* qb   = (float*)p;
    cudaGetSymbolAddress(&p, g_kbuf); float* kb   = (float*)p;
    cudaGetSymbolAddress(&p, g_vt);   float* vt   = (float*)p;
    cudaGetSymbolAddress(&p, g_om);   float* om   = (float*)p;
    cudaGetSymbolAddress(&p, g_attn); float* attn_scratch = (float*)p;
    cudaGetSymbolAddress(&p, g_hsr);  float* hsr  = (float*)p;
    cudaGetSymbolAddress(&p, g_wqkd); float* wqkd = (float*)p;
    cudaGetSymbolAddress(&p, g_wqu);  float* wqu  = (float*)p;
    cudaGetSymbolAddress(&p, g_wku);  float* wku  = (float*)p;
    cudaGetSymbolAddress(&p, g_wo);   float* wo   = (float*)p;

    cudaFuncSetAttribute(mma_gemm, cudaFuncAttributeMaxDynamicSharedMemorySize, SMEMF);

    // one-time streams/events (host resources only; no device memory)
    static cudaStream_t s1 = 0, s2 = 0;
    static cudaEvent_t e0 = 0, eW = 0, eDn = 0, eKv = 0, eVt = 0;
    if (!s1) {
        cudaStreamCreateWithFlags(&s1, cudaStreamNonBlocking);
        cudaStreamCreateWithFlags(&s2, cudaStreamNonBlocking);
        cudaEventCreateWithFlags(&e0,  cudaEventDisableTiming);
        cudaEventCreateWithFlags(&eW,  cudaEventDisableTiming);
        cudaEventCreateWithFlags(&eDn, cudaEventDisableTiming);
        cudaEventCreateWithFlags(&eKv, cudaEventDisableTiming);
        cudaEventCreateWithFlags(&eVt, cudaEventDisableTiming);
    }

    const size_t need = (size_t)TOK * HID + (size_t)BHN * SEQ * SEQ;
    float* attn_out = ((size_t)out_size >= need)
                    ? (float*)d_out + (size_t)TOK * HID
                    : attn_scratch;

    const float qk_scale = 1.0f / sqrtf((float)DQK);

    // fork s1 from origin
    cudaEventRecord(e0, 0);
    cudaStreamWaitEvent(s1, e0, 0);

    // s1: weight rounds not needed by the down GEMM
    { long n4 = (long)(NH*DQK)*QLORA/4; round4<<<cdiv(n4,256),256,0,s1>>>((const float4*)w_q_up, (float4*)wqu, n4); }
    { long n4 = (long)(NH*256)*KVLORA/4; round4<<<cdiv(n4,256),256,0,s1>>>((const float4*)w_kv_up, (float4*)wku, n4); }
    { long n4 = (long)HID*(NH*DV)/4;    round4<<<cdiv(n4,256),256,0,s1>>>((const float4*)w_out, (float4*)wo, n4); }
    cudaEventRecord(eW, s1);

    // s0: inputs needed by down GEMM
    init_rope<<<1, 32>>>();
    { long n4 = (long)TOK*HID/4;              round4<<<cdiv(n4,256),256>>>((const float4*)hs, (float4*)hsr, n4); }
    { long n4 = (long)QLORA*HID/4;            round4<<<cdiv(n4,256),256>>>((const float4*)w_q_down, (float4*)wqkd, n4); }
    { long n4 = (long)(KVLORA+ROPE_D)*HID/4;  round4<<<cdiv(n4,256),256>>>((const float4*)w_kv_down, (float4*)(wqkd + (size_t)QLORA*HID), n4); }

    // down: qc = hs @ concat(wq,wkv)^T
    mma_gemm<<<dim3(cdiv(QKVD,128), TOK/128), 256, SMEMF>>>(
        hsr, wqkd, qc,
        HID, 0, HID, 0, QKVD, 0, 0, 1,
        TOK, QKVD, HID, 1.f, 0, 0);
    cudaEventRecord(eDn, 0);

    // s2: KV path (rmsnorm_kv -> kv_up -> vtrans)
    cudaStreamWaitEvent(s2, eDn, 0);
    cudaStreamWaitEvent(s2, eW, 0);
    rmsnorm_round<<<TOK, 256, 0, s2>>>(qc + QLORA, QKVD, kv_norm_w, ckn, KVLORA, KVLORA);
    mma_gemm<<<dim3((NH*256)/128, TOK/128), 256, SMEMF, s2>>>(
        ckn, wku, kv,
        KVLORA, 0, KVLORA, 0, NH*256, 0, 0, 1,
        TOK, NH*256, KVLORA, 1.f, 0, 0);
    cudaEventRecord(eKv, s2);
    {
        long total = (long)BHN * DV * SEQ;
        vtrans<<<(int)((total + 255) / 256), 256, 0, s2>>>();
    }
    cudaEventRecord(eVt, s2);

    // s0: Q path
    cudaStreamWaitEvent(0, eW, 0);
    rmsnorm_round<<<TOK, 256>>>(qc, QKVD, q_norm_w, q1n, QLORA, QLORA);
    mma_gemm<<<dim3((NH*DQK)/128, TOK/128), 256, SMEMF>>>(
        q1n, wqu, q,
        QLORA, 0, QLORA, 0, NH*DQK, 0, 0, 1,
        TOK, NH*DQK, QLORA, 1.f, 0, 0);

    // rope needs q (s0) + kv (s2) + qc rope cols (s0)
    cudaStreamWaitEvent(0, eKv, 0);
    rope_pack<<<BHN*SEQ, 256>>>();

    // scores
    mma_gemm<<<dim3(SEQ/128, SEQ/128, BHN), 256, SMEMF>>>(
        qb, kb, attn_out,
        DQK, (long)SEQ*DQK, DQK, (long)SEQ*DQK,
        SEQ, (long)SEQ*SEQ, 0, 1,
        SEQ, SEQ, DQK, qk_scale, 1, 0);

    softmax_causal<<<BHN*SEQ, 256>>>(attn_out);

    // PV needs vtrans (s2)
    cudaStreamWaitEvent(0, eVt, 0);
    mma_gemm<<<dim3(DV/128, SEQ/128, BHN), 256, SMEMF>>>(
        attn_out, vt, om,
        SEQ, (long)SEQ*SEQ, SEQ, (long)DV*SEQ,
        NH*DV, (long)SEQ*NH*DV, DV, NH,
        SEQ, DV, SEQ, 1.f, 2, 1);

    // out = om @ w_out^T
    mma_gemm<<<dim3(HID/128, TOK/128), 256, SMEMF>>>(
        om, wo, out_final,
        NH*DV, 0, NH*DV, 0, HID, 0, 0, 1,
        TOK, HID, NH*DV, 1.f, 0, 0);
}